// round 15
// baseline (speedup 1.0000x reference)
#include <cuda_runtime.h>
#include <cuda_bf16.h>
#include <math.h>
#include <cstdint>

// Problem constants
#define NB     8
#define LSEQ   2048
#define BL     16384          // NB*LSEQ
#define DLEN   512
#define DM     256
#define NPROJ  1024           // Q|K|V|Add concatenated
#define MRF    256
#define TWOM   512
#define NCLASS 64
#define FTOT   (LSEQ*DM)      // 524288 flattened features per batch

#define TWO_PI 6.28318530717958647692f
#define LSPLIT 4              // L-splits for kv kernel

// ---------------- device scratch (allocation-free rule: static globals) ----
__device__ float g_qkva[BL * NPROJ];      // 64 MB : [row,1024]; only V|Add written
__device__ float g_ssq[2 * BL];           // fused row sum-of-squares (Q then K)
__device__ float g_qp[BL * TWOM];         // 32 MB (fp32 — num reads it)
__device__ float g_ksum[NB * TWOM];
__device__ float g_kv[NB * TWOM * DM];    // 4 MB
__device__ float g_out[BL * DM];          // 16 MB

// bf16 hi/lo split tensors
__device__ __nv_bfloat16 g_x_hi[BL * DLEN],  g_x_lo[BL * DLEN];     // 16+16 MB
__device__ __nv_bfloat16 g_w_hi[1024 * DLEN], g_w_lo[1024 * DLEN];  // 1+1 MB
__device__ __nv_bfloat16 g_rf_hi[MRF * MRF],  g_rf_lo[MRF * MRF];
__device__ __nv_bfloat16 g_qk_hi[BL * 512],  g_qk_lo[BL * 512];     // [row][Q|K]
__device__ __nv_bfloat16 g_kp_hi[BL * TWOM], g_kp_lo[BL * TWOM];    // phi(k), 16+16 MB

// ============================================================================
// helpers
// ============================================================================
__device__ __forceinline__ uint32_t smem_u32(const void* p) {
    uint32_t a;
    asm("{ .reg .u64 t; cvta.to.shared.u64 t, %1; cvt.u32.u64 %0, t; }" : "=r"(a) : "l"(p));
    return a;
}
__device__ __forceinline__ void ldmx4(uint32_t r[4], const void* p) {
    uint32_t a = smem_u32(p);
    asm volatile("ldmatrix.sync.aligned.m8n8.x4.shared.b16 {%0,%1,%2,%3}, [%4];"
                 : "=r"(r[0]), "=r"(r[1]), "=r"(r[2]), "=r"(r[3]) : "r"(a));
}
__device__ __forceinline__ void ldmx4t(uint32_t r[4], const void* p) {
    uint32_t a = smem_u32(p);
    asm volatile("ldmatrix.sync.aligned.m8n8.x4.trans.shared.b16 {%0,%1,%2,%3}, [%4];"
                 : "=r"(r[0]), "=r"(r[1]), "=r"(r[2]), "=r"(r[3]) : "r"(a));
}
__device__ __forceinline__ void mma16816(float d[4], const uint32_t a[4],
                                         uint32_t b0, uint32_t b1) {
    asm volatile(
        "mma.sync.aligned.m16n8k16.row.col.f32.bf16.bf16.f32 "
        "{%0,%1,%2,%3}, {%4,%5,%6,%7}, {%8,%9}, {%0,%1,%2,%3};"
        : "+f"(d[0]), "+f"(d[1]), "+f"(d[2]), "+f"(d[3])
        : "r"(a[0]), "r"(a[1]), "r"(a[2]), "r"(a[3]), "r"(b0), "r"(b1));
}
#define CP16(dst, src) asm volatile("cp.async.cg.shared.global [%0], [%1], 16;" :: "r"(dst), "l"(src))
#define CP_COMMIT()    asm volatile("cp.async.commit_group;" ::: "memory")
#define CP_WAIT1()     asm volatile("cp.async.wait_group 1;" ::: "memory")
#define CP_WAIT0()     asm volatile("cp.async.wait_group 0;" ::: "memory")

#define TPAD 40
#define KTP  136
#define KTPB 72

__device__ __forceinline__ void cvt8(const float xs[8], uint32_t hw[4], uint32_t lw[4]) {
#pragma unroll
    for (int q = 0; q < 4; q++) {
        __nv_bfloat16 h0 = __float2bfloat16_rn(xs[2*q]);
        __nv_bfloat16 h1 = __float2bfloat16_rn(xs[2*q+1]);
        hw[q] = (uint32_t)__bfloat16_as_ushort(h0) | ((uint32_t)__bfloat16_as_ushort(h1) << 16);
        __nv_bfloat16 l0 = __float2bfloat16_rn(xs[2*q]   - __bfloat162float(h0));
        __nv_bfloat16 l1 = __float2bfloat16_rn(xs[2*q+1] - __bfloat162float(h1));
        lw[q] = (uint32_t)__bfloat16_as_ushort(l0) | ((uint32_t)__bfloat16_as_ushort(l1) << 16);
    }
}
__device__ __forceinline__ uint32_t pack_hl(float v0, float v1, uint32_t& lo_out) {
    __nv_bfloat16 h0 = __float2bfloat16_rn(v0);
    __nv_bfloat16 h1 = __float2bfloat16_rn(v1);
    __nv_bfloat16 l0 = __float2bfloat16_rn(v0 - __bfloat162float(h0));
    __nv_bfloat16 l1 = __float2bfloat16_rn(v1 - __bfloat162float(h1));
    lo_out = (uint32_t)__bfloat16_as_ushort(l0) | ((uint32_t)__bfloat16_as_ushort(l1) << 16);
    return (uint32_t)__bfloat16_as_ushort(h0) | ((uint32_t)__bfloat16_as_ushort(h1) << 16);
}
__device__ __forceinline__ float bf_sum2(uint32_t w) {
    return __bfloat162float(__ushort_as_bfloat16((unsigned short)(w & 0xFFFFu)))
         + __bfloat162float(__ushort_as_bfloat16((unsigned short)(w >> 16)));
}

// ============================================================================
// cp.async ping-pong GEMM core (128x128, NT): 8 warps 2x4, warp 64x32.
// ============================================================================
#define ST2_AHI 0
#define ST2_ALO (128 * TPAD)
#define ST2_BHI (2 * 128 * TPAD)
#define ST2_BLO (3 * 128 * TPAD)
#define ST2_SZ  (4 * 128 * TPAD)
#define SMEM_DYN2 (2 * ST2_SZ * 2)

template<int KCH>
__device__ __forceinline__ void gemm_core_cp2(
    const __nv_bfloat16* __restrict__ Ahi, const __nv_bfloat16* __restrict__ Alo, int astr,
    const __nv_bfloat16* __restrict__ Bhi, const __nv_bfloat16* __restrict__ Blo, int bstr,
    float acc[4][4][4], __nv_bfloat16* sm)
{
    const int tid = threadIdx.x, wid = tid >> 5, lane = tid & 31;
    const int wm = (wid >> 2) * 64, wn = (wid & 3) * 32;
    const int arow = wm + (lane & 15), akc = (lane >> 4) * 8;
    const int brow = wn + (lane >> 4) * 8 + (lane & 7), bkc = ((lane >> 3) & 1) * 8;

    const int rT = tid >> 1, cT = (tid & 1) * 2;

    auto issue = [&](int st, int k0) {
        __nv_bfloat16* base = sm + st * ST2_SZ;
#pragma unroll
        for (int j = 0; j < 2; j++) {
            int c = cT + j;
            CP16(smem_u32(base + ST2_AHI + rT * TPAD + c * 8), Ahi + (size_t)rT * astr + k0 + c * 8);
            CP16(smem_u32(base + ST2_ALO + rT * TPAD + c * 8), Alo + (size_t)rT * astr + k0 + c * 8);
            CP16(smem_u32(base + ST2_BHI + rT * TPAD + c * 8), Bhi + (size_t)rT * bstr + k0 + c * 8);
            CP16(smem_u32(base + ST2_BLO + rT * TPAD + c * 8), Blo + (size_t)rT * bstr + k0 + c * 8);
        }
        CP_COMMIT();
    };

    issue(0, 0);
    for (int ch = 0; ch < KCH; ch++) {
        if (ch + 1 < KCH) { issue((ch + 1) & 1, (ch + 1) * 32); CP_WAIT1(); }
        else              { CP_WAIT0(); }
        __syncthreads();

        const __nv_bfloat16* base = sm + (ch & 1) * ST2_SZ;
#pragma unroll
        for (int ks = 0; ks < 2; ks++) {
            const int kc = ks * 16;
            uint32_t ahi[4][4], alo[4][4];
#pragma unroll
            for (int mi = 0; mi < 4; mi++) {
                const int off = (arow + mi * 16) * TPAD + kc + akc;
                ldmx4(ahi[mi], base + ST2_AHI + off);
                ldmx4(alo[mi], base + ST2_ALO + off);
            }
            uint32_t bh[2][4], bl[2][4];
#pragma unroll
            for (int np = 0; np < 2; np++) {
                const int off = (brow + np * 16) * TPAD + kc + bkc;
                ldmx4(bh[np], base + ST2_BHI + off);
                ldmx4(bl[np], base + ST2_BLO + off);
            }
#pragma unroll
            for (int mi = 0; mi < 4; mi++)
#pragma unroll
                for (int nj = 0; nj < 4; nj++) {
                    const int np = nj >> 1, o = (nj & 1) * 2;
                    mma16816(acc[mi][nj], ahi[mi], bh[np][o], bh[np][o+1]);
                    mma16816(acc[mi][nj], ahi[mi], bl[np][o], bl[np][o+1]);
                    mma16816(acc[mi][nj], alo[mi], bh[np][o], bh[np][o+1]);
                }
        }
        __syncthreads();
    }
}

// ============================================================================
// Kernel -1: convert inputs + fused zero/init duties.
// ============================================================================
#define NXE (BL * DLEN)
#define NWE (1024 * DLEN)
#define NRE (MRF * MRF)
#define CVT_BLOCKS ((NXE + NWE + NRE) / 8 / 256)

__global__ void k_cvt(const float* __restrict__ X,
                      const float* __restrict__ Wq, const float* __restrict__ Wk,
                      const float* __restrict__ Wv, const float* __restrict__ Wa,
                      const float* __restrict__ rf,
                      float* __restrict__ out, const float* __restrict__ bf)
{
    int idx = blockIdx.x * 256 + threadIdx.x;
    if (idx < NB * TWOM * DM / 4)
        ((float4*)g_kv)[idx] = make_float4(0.f, 0.f, 0.f, 0.f);
    if (idx < 2 * BL / 4)
        ((float4*)g_ssq)[idx] = make_float4(0.f, 0.f, 0.f, 0.f);
    if (idx < NB * TWOM / 4)
        ((float4*)g_ksum)[idx] = make_float4(0.f, 0.f, 0.f, 0.f);
    if (idx < NB * NCLASS)
        out[idx] = bf[idx & 63];

    size_t base = ((size_t)blockIdx.x * 256 + threadIdx.x) * 8;
    const float* src;
    __nv_bfloat16 *dhi, *dlo;
    if (base < NXE) {
        src = X + base; dhi = g_x_hi + base; dlo = g_x_lo + base;
    } else if (base < NXE + NWE) {
        size_t off = base - NXE;
        int sel = (int)(off >> 17);
        const float* W = (sel == 0) ? Wq : (sel == 1) ? Wk : (sel == 2) ? Wv : Wa;
        src = W + (off & 131071); dhi = g_w_hi + off; dlo = g_w_lo + off;
    } else {
        size_t off = base - NXE - NWE;
        src = rf + off; dhi = g_rf_hi + off; dlo = g_rf_lo + off;
    }
    float4 u = *(const float4*)src, v = *(const float4*)(src + 4);
    float xs[8] = {u.x, u.y, u.z, u.w, v.x, v.y, v.z, v.w};
    uint32_t hw[4], lw[4];
    cvt8(xs, hw, lw);
    *(uint4*)dhi = make_uint4(hw[0], hw[1], hw[2], hw[3]);
    *(uint4*)dlo = make_uint4(lw[0], lw[1], lw[2], lw[3]);
}

// ============================================================================
// Kernel 1: proj (128x128 tiles). bn 0..3: Q|K bf16 hi/lo + fused ssq;
// bn 4..7: V|Add fp32.
// ============================================================================
__global__ void __launch_bounds__(256, 2) k_proj_mma()
{
    extern __shared__ __nv_bfloat16 sm[];
    const int bn = blockIdx.x;            // 0..7
    const int bm = blockIdx.y;            // 0..127

    const __nv_bfloat16* Ah = g_x_hi + (size_t)bm * 128 * DLEN;
    const __nv_bfloat16* Al = g_x_lo + (size_t)bm * 128 * DLEN;
    const __nv_bfloat16* Bh = g_w_hi + (size_t)bn * 128 * DLEN;
    const __nv_bfloat16* Bl = g_w_lo + (size_t)bn * 128 * DLEN;

    float acc[4][4][4] = {};
    gemm_core_cp2<16>(Ah, Al, DLEN, Bh, Bl, DLEN, acc, sm);

    const int tid = threadIdx.x, wid = tid >> 5, lane = tid & 31;
    const int r0 = bm * 128 + (wid >> 2) * 64 + (lane >> 2);
    const int c0 = bn * 128 + (wid & 3) * 32 + (lane & 3) * 2;

    if (bn < 4) {   // Q|K -> bf16 hi/lo + fused row sum-of-squares
        const int isK = bn >> 1;
#pragma unroll
        for (int mi = 0; mi < 4; mi++)
#pragma unroll
            for (int h = 0; h < 2; h++) {
                int r = r0 + mi * 16 + h * 8;
                float ss = 0.f;
#pragma unroll
                for (int nj = 0; nj < 4; nj++) {
                    int c = c0 + nj * 8;
                    float v0 = acc[mi][nj][h*2], v1 = acc[mi][nj][h*2+1];
                    ss = fmaf(v0, v0, ss);
                    ss = fmaf(v1, v1, ss);
                    uint32_t lo, hi = pack_hl(v0, v1, lo);
                    size_t idx = (size_t)r * 512 + c;
                    *(uint32_t*)(g_qk_hi + idx) = hi;
                    *(uint32_t*)(g_qk_lo + idx) = lo;
                }
                ss += __shfl_xor_sync(0xFFFFFFFFu, ss, 1);
                ss += __shfl_xor_sync(0xFFFFFFFFu, ss, 2);
                if ((lane & 3) == 0)
                    atomicAdd(&g_ssq[isK * BL + r], ss);
            }
    } else {        // V|Add -> fp32 qkva, cols 512..1023
#pragma unroll
        for (int mi = 0; mi < 4; mi++)
#pragma unroll
            for (int nj = 0; nj < 4; nj++) {
                int r = r0 + mi * 16, c = c0 + nj * 8;
                *(float2*)&g_qkva[(size_t)r * NPROJ + c]       = make_float2(acc[mi][nj][0], acc[mi][nj][1]);
                *(float2*)&g_qkva[(size_t)(r + 8) * NPROJ + c] = make_float2(acc[mi][nj][2], acc[mi][nj][3]);
            }
    }
}

// ============================================================================
// Kernel 3: phi. isQ -> fp32 g_qp; isK -> bf16 hi/lo g_kp_hi/lo.
// Inline expscale.
// ============================================================================
__global__ void __launch_bounds__(256, 2) k_phi_mma()
{
    extern __shared__ __nv_bfloat16 sm[];
    const int bn = blockIdx.x;            // 0..1
    const int bm = blockIdx.y;            // 0..127
    const int isK = blockIdx.z;

    const __nv_bfloat16* Ah = g_qk_hi + (size_t)bm * 128 * 512 + (isK ? DM : 0);
    const __nv_bfloat16* Al = g_qk_lo + (size_t)bm * 128 * 512 + (isK ? DM : 0);
    const __nv_bfloat16* Bh = g_rf_hi + (size_t)bn * 128 * MRF;
    const __nv_bfloat16* Bl = g_rf_lo + (size_t)bn * 128 * MRF;

    float acc[4][4][4] = {};
    gemm_core_cp2<8>(Ah, Al, 512, Bh, Bl, MRF, acc, sm);

    const float* SQ = g_ssq + isK * BL;

    const int tid = threadIdx.x, wid = tid >> 5, lane = tid & 31;
    const int r0 = bm * 128 + (wid >> 2) * 64 + (lane >> 2);
    const int c0 = bn * 128 + (wid & 3) * 32 + (lane & 3) * 2;   // feature 0..255
#pragma unroll
    for (int mi = 0; mi < 4; mi++) {
        int r = r0 + mi * 16;
        float sa = expf(0.5f * SQ[r])     * 0.0625f;
        float sb = expf(0.5f * SQ[r + 8]) * 0.0625f;
#pragma unroll
        for (int nj = 0; nj < 4; nj++) {
            int c = c0 + nj * 8;
            float s0, cz0, s1, cz1, s2, cz2, s3, cz3;
            sincosf(TWO_PI * acc[mi][nj][0], &s0, &cz0);
            sincosf(TWO_PI * acc[mi][nj][1], &s1, &cz1);
            sincosf(TWO_PI * acc[mi][nj][2], &s2, &cz2);
            sincosf(TWO_PI * acc[mi][nj][3], &s3, &cz3);
            float a0 = s0 * sa,  a1 = s1 * sa,  e0 = cz0 * sa, e1 = cz1 * sa;
            float b0 = s2 * sb,  b1 = s3 * sb,  f0 = cz2 * sb, f1 = cz3 * sb;
            if (isK) {
                uint32_t lo, hi;
                size_t ia = (size_t)r * TWOM + c;
                hi = pack_hl(a0, a1, lo);
                *(uint32_t*)(g_kp_hi + ia) = hi; *(uint32_t*)(g_kp_lo + ia) = lo;
                hi = pack_hl(e0, e1, lo);
                *(uint32_t*)(g_kp_hi + ia + DM) = hi; *(uint32_t*)(g_kp_lo + ia + DM) = lo;
                size_t ib = (size_t)(r + 8) * TWOM + c;
                hi = pack_hl(b0, b1, lo);
                *(uint32_t*)(g_kp_hi + ib) = hi; *(uint32_t*)(g_kp_lo + ib) = lo;
                hi = pack_hl(f0, f1, lo);
                *(uint32_t*)(g_kp_hi + ib + DM) = hi; *(uint32_t*)(g_kp_lo + ib + DM) = lo;
            } else {
                float* rowa = g_qp + (size_t)r * TWOM;
                float* rowb = g_qp + (size_t)(r + 8) * TWOM;
                *(float2*)&rowa[c]      = make_float2(a0, a1);
                *(float2*)&rowa[c + DM] = make_float2(e0, e1);
                *(float2*)&rowb[c]      = make_float2(b0, b1);
                *(float2*)&rowb[c + DM] = make_float2(f0, f1);
            }
        }
    }
}

// ============================================================================
// Kernel 4: kv. A = kp bf16 hi/lo via cp.async ping-pong (trans);
// B = v fp32 register-prefetch cvt8 (trans). Fused ksum from A fragments
// (wn==0 warps, blockIdx.x==0 only). Atomic fp32 accumulate into g_kv.
// ============================================================================
#define KVA_STG (2 * 32 * KTP)     // one stage: hi + lo

__global__ void __launch_bounds__(256, 2) k_kv_mma()
{
    __shared__ __nv_bfloat16 sA[2 * KVA_STG];              // ping-pong A
    __shared__ __nv_bfloat16 sBhi[32 * KTPB], sBlo[32 * KTPB];

    const int d0 = blockIdx.x * 64;
    const int m0 = blockIdx.y * 128;
    const int b  = blockIdx.z >> 2;
    const int sp = blockIdx.z & 3;
    const size_t rowb = (size_t)b * LSEQ;
    const float* vb = g_qkva + rowb * NPROJ + 2 * DM + d0;

    const int tid = threadIdx.x, wid = tid >> 5, lane = tid & 31;
    const int g8 = lane >> 3, r8 = lane & 7;
    const int wm = (wid >> 2) * 64, wn = (wid & 3) * 16;

    float acc[4][2][4] = {};
    float ksm[4][2] = {};

    const int rA = tid >> 3, cA = tid & 7;        // A: 32 rows x 16 16B-chunks (2/thread)
    const int brow0 = tid >> 3, bcol8 = (tid & 7) * 8;

    auto issueA = [&](int st, int l0) {
        __nv_bfloat16* base = sA + st * KVA_STG;
        size_t src = (rowb + l0 + rA) * TWOM + m0;
#pragma unroll
        for (int j = 0; j < 2; j++) {
            int c = cA + j * 8;
            CP16(smem_u32(base + rA * KTP + c * 8),            g_kp_hi + src + c * 8);
            CP16(smem_u32(base + 32 * KTP + rA * KTP + c * 8), g_kp_lo + src + c * 8);
        }
        CP_COMMIT();
    };

    const int ch0 = sp * (LSEQ / 32 / LSPLIT);
    const int nch = LSEQ / 32 / LSPLIT;

    issueA(0, ch0 * 32);
    float pb[8];
    {
        const float* q = vb + (size_t)(ch0 * 32 + brow0) * NPROJ + bcol8;
        *(float4*)&pb[0] = *(const float4*)q;
        *(float4*)&pb[4] = *(const float4*)(q + 4);
    }

    for (int i = 0; i < nch; i++) {
        {   // store B from prefetched registers
            uint32_t hw[4], lw[4];
            cvt8(pb, hw, lw);
            int idx = brow0 * KTPB + bcol8;
            *(uint4*)(sBhi + idx) = make_uint4(hw[0], hw[1], hw[2], hw[3]);
            *(uint4*)(sBlo + idx) = make_uint4(lw[0], lw[1], lw[2], lw[3]);
        }
        if (i + 1 < nch) { issueA((i + 1) & 1, (ch0 + i + 1) * 32); CP_WAIT1(); }
        else             { CP_WAIT0(); }
        __syncthreads();

        if (i + 1 < nch) {   // prefetch next B (overlaps MMA)
            const float* q = vb + (size_t)((ch0 + i + 1) * 32 + brow0) * NPROJ + bcol8;
            *(float4*)&pb[0] = *(const float4*)q;
            *(float4*)&pb[4] = *(const float4*)(q + 4);
        }

        const __nv_bfloat16* baseA = sA + (i & 1) * KVA_STG;
#pragma unroll
        for (int ks = 0; ks < 2; ks++) {
            const int kc = ks * 16;
            uint32_t ahi[4][4], alo[4][4];
#pragma unroll
            for (int mi = 0; mi < 4; mi++) {
                const int off = (kc + r8 + (g8 >> 1) * 8) * KTP + wm + mi * 16 + (g8 & 1) * 8;
                ldmx4t(ahi[mi], baseA + off);
                ldmx4t(alo[mi], baseA + 32 * KTP + off);
            }
            uint32_t bhi[4], blo[4];
            {
                const int off = (kc + r8 + (g8 & 1) * 8) * KTPB + wn + (g8 >> 1) * 8;
                ldmx4t(bhi, sBhi + off);
                ldmx4t(blo, sBlo + off);
            }
#pragma unroll
            for (int mi = 0; mi < 4; mi++)
#pragma unroll
                for (int nj = 0; nj < 2; nj++) {
                    const int o = nj * 2;
                    mma16816(acc[mi][nj], ahi[mi], bhi[o], bhi[o+1]);
                    mma16816(acc[mi][nj], ahi[mi], blo[o], blo[o+1]);
                    mma16816(acc[mi][nj], alo[mi], bhi[o], bhi[o+1]);
                }
            if (blockIdx.x == 0 && wn == 0) {   // fused ksum from A fragments
#pragma unroll
                for (int mi = 0; mi < 4; mi++) {
                    // regs 0,2: m = lane>>2; regs 1,3: m = (lane>>2)+8
                    ksm[mi][0] += bf_sum2(ahi[mi][0]) + bf_sum2(ahi[mi][2])
                                + bf_sum2(alo[mi][0]) + bf_sum2(alo[mi][2]);
                    ksm[mi][1] += bf_sum2(ahi[mi][1]) + bf_sum2(ahi[mi][3])
                                + bf_sum2(alo[mi][1]) + bf_sum2(alo[mi][3]);
                }
            }
        }
        __syncthreads();
    }

    const int rr0 = m0 + wm + (lane >> 2);
    const int cc0 = d0 + wn + (lane & 3) * 2;
#pragma unroll
    for (int mi = 0; mi < 4; mi++)
#pragma unroll
        for (int nj = 0; nj < 2; nj++) {
            int r = rr0 + mi * 16, c = cc0 + nj * 8;
            float* p0 = &g_kv[((size_t)b * TWOM + r) * DM + c];
            float* p1 = &g_kv[((size_t)b * TWOM + r + 8) * DM + c];
            atomicAdd(p0,     acc[mi][nj][0]);
            atomicAdd(p0 + 1, acc[mi][nj][1]);
            atomicAdd(p1,     acc[mi][nj][2]);
            atomicAdd(p1 + 1, acc[mi][nj][3]);
        }

    if (blockIdx.x == 0 && wn == 0) {
#pragma unroll
        for (int mi = 0; mi < 4; mi++) {
            float s0 = ksm[mi][0], s1 = ksm[mi][1];
            s0 += __shfl_xor_sync(0xFFFFFFFFu, s0, 1);
            s0 += __shfl_xor_sync(0xFFFFFFFFu, s0, 2);
            s1 += __shfl_xor_sync(0xFFFFFFFFu, s1, 1);
            s1 += __shfl_xor_sync(0xFFFFFFFFu, s1, 2);
            if ((lane & 3) == 0) {
                int m = m0 + wm + mi * 16 + (lane >> 2);
                atomicAdd(&g_ksum[b * TWOM + m],     s0);
                atomicAdd(&g_ksum[b * TWOM + m + 8], s1);
            }
        }
    }
}

// ============================================================================
// Kernel 5 (mma): num + fused denom + epilogue  (unchanged; reads fp32 qp/kv)
// ============================================================================
__global__ void __launch_bounds__(256, 2) k_num_mma(const float* __restrict__ b_add)
{
    __shared__ __nv_bfloat16 sAhi[128 * TPAD], sAlo[128 * TPAD];
    __shared__ __nv_bfloat16 sBhi[32 * KTPB],  sBlo[32 * KTPB];
    __shared__ float red2[128][4];

    const int d0 = blockIdx.x * 64;
    const int lt = blockIdx.y * 128;
    const int b  = blockIdx.z;
    const float* qpb = g_qp + (size_t)(b * LSEQ + lt) * TWOM;
    const float* kvb = g_kv + (size_t)b * TWOM * DM + d0;
    const float* ksb = g_ksum + b * TWOM;

    const int tid = threadIdx.x, wid = tid >> 5, lane = tid & 31;
    const int g8 = lane >> 3, r8 = lane & 7;
    const int wm = (wid >> 2) * 64, wn = (wid & 3) * 16;
    const int arow = wm + (lane & 15);
    const int akc  = (lane >> 4) * 8;

    float acc[4][2][4] = {};
    float dn[2] = {0.f, 0.f};

    const int srow0 = tid >> 2, scol8 = (tid & 3) * 8;
    const int brow0 = tid >> 3, bcol8 = (tid & 7) * 8;

    float pa[2][8], pb[8];
#pragma unroll
    for (int i = 0; i < 2; i++) {
        const float* p = qpb + (size_t)(srow0 + i * 64) * TWOM + scol8;
        *(float4*)&pa[i][0] = *(const float4*)p;
        *(float4*)&pa[i][4] = *(const float4*)(p + 4);
    }
    {
        const float* q = kvb + (size_t)brow0 * DM + bcol8;
        *(float4*)&pb[0] = *(const float4*)q;
        *(float4*)&pb[4] = *(const float4*)(q + 4);
    }

    for (int ch = 0; ch < TWOM / 32; ch++) {
        const int k0 = ch * 32;
#pragma unroll
        for (int i = 0; i < 2; i++) {
            int row = srow0 + i * 64;
            uint32_t hw[4], lw[4];
            cvt8(pa[i], hw, lw);
            const float* ks = ksb + k0 + scol8;
#pragma unroll
            for (int q = 0; q < 8; q++) dn[i] = fmaf(pa[i][q], ks[q], dn[i]);
            *(uint4*)(sAhi + row * TPAD + scol8) = make_uint4(hw[0], hw[1], hw[2], hw[3]);
            *(uint4*)(sAlo + row * TPAD + scol8) = make_uint4(lw[0], lw[1], lw[2], lw[3]);
        }
        {
            uint32_t hw[4], lw[4];
            cvt8(pb, hw, lw);
            int idx = brow0 * KTPB + bcol8;
            *(uint4*)(sBhi + idx) = make_uint4(hw[0], hw[1], hw[2], hw[3]);
            *(uint4*)(sBlo + idx) = make_uint4(lw[0], lw[1], lw[2], lw[3]);
        }
        __syncthreads();

        if (ch + 1 < TWOM / 32) {
            const int k1 = (ch + 1) * 32;
#pragma unroll
            for (int i = 0; i < 2; i++) {
                const float* p = qpb + (size_t)(srow0 + i * 64) * TWOM + k1 + scol8;
                *(float4*)&pa[i][0] = *(const float4*)p;
                *(float4*)&pa[i][4] = *(const float4*)(p + 4);
            }
            const float* q = kvb + (size_t)(k1 + brow0) * DM + bcol8;
            *(float4*)&pb[0] = *(const float4*)q;
            *(float4*)&pb[4] = *(const float4*)(q + 4);
        }

#pragma unroll
        for (int ks2 = 0; ks2 < 2; ks2++) {
            const int kc = ks2 * 16;
            uint32_t ahi[4][4], alo[4][4];
#pragma unroll
            for (int mi = 0; mi < 4; mi++) {
                const int off = (arow + mi * 16) * TPAD + kc + akc;
                ldmx4(ahi[mi], sAhi + off);
                ldmx4(alo[mi], sAlo + off);
            }
            uint32_t bhi[4], blo[4];
            {
                const int off = (kc + r8 + (g8 & 1) * 8) * KTPB + wn + (g8 >> 1) * 8;
                ldmx4t(bhi, sBhi + off);
                ldmx4t(blo, sBlo + off);
            }
#pragma unroll
            for (int mi = 0; mi < 4; mi++)
#pragma unroll
                for (int nj = 0; nj < 2; nj++) {
                    const int o = nj * 2;
                    mma16816(acc[mi][nj], ahi[mi], bhi[o], bhi[o+1]);
                    mma16816(acc[mi][nj], ahi[mi], blo[o], blo[o+1]);
                    mma16816(acc[mi][nj], alo[mi], bhi[o], bhi[o+1]);
                }
        }
        __syncthreads();
    }

    red2[srow0][tid & 3]      = dn[0];
    red2[srow0 + 64][tid & 3] = dn[1];
    __syncthreads();

    const int rr0 = wm + (lane >> 2);
    const int cc0 = d0 + wn + (lane & 3) * 2;
#pragma unroll
    for (int mi = 0; mi < 4; mi++) {
#pragma unroll
        for (int h = 0; h < 2; h++) {
            int rloc = rr0 + mi * 16 + h * 8;
            float den = red2[rloc][0] + red2[rloc][1] + red2[rloc][2] + red2[rloc][3];
            float inv = 1.0f / den;
            int rg = b * LSEQ + lt + rloc;
            const float* addp = g_qkva + (size_t)rg * NPROJ + 3 * DM;
            float* orow = g_out + (size_t)rg * DM;
#pragma unroll
            for (int nj = 0; nj < 2; nj++) {
                int c = cc0 + nj * 8;
                float v0 = acc[mi][nj][h*2]   * inv + addp[c]     + b_add[c];
                float v1 = acc[mi][nj][h*2+1] * inv + addp[c + 1] + b_add[c + 1];
                *(float2*)&orow[c] = make_float2(v0, v1);
            }
        }
    }
}

// ============================================================================
// Kernel 6: final GEMM (split-K atomics; out pre-seeded with b_final by k_cvt)
// ============================================================================
__global__ void __launch_bounds__(256) k_final(const float* __restrict__ Wf,
                                               float* __restrict__ out)
{
    __shared__ float Ws[64][130];
    __shared__ float Os[8][132];

    const int tid = threadIdx.x;
    const int c  = tid & 63;
    const int bb = tid >> 6;
    float acc0 = 0.f, acc1 = 0.f;
    const int f0 = blockIdx.x * 1024;

    for (int t = 0; t < 1024; t += 128) {
        const int fbase = f0 + t;
#pragma unroll
        for (int i = 0; i < 8; i++) {
            int v = tid + i * 256;
            int cc = v >> 5, f4 = (v & 31) * 4;
            float4 w = *(const float4*)(Wf + (size_t)cc * FTOT + fbase + f4);
            Ws[cc][f4] = w.x; Ws[cc][f4+1] = w.y; Ws[cc][f4+2] = w.z; Ws[cc][f4+3] = w.w;
        }
        {
            int v = tid;
            int bo = v >> 5, f4 = (v & 31) * 4;
            float4 o = *(const float4*)(g_out + (size_t)bo * FTOT + fbase + f4);
            Os[bo][f4] = o.x; Os[bo][f4+1] = o.y; Os[bo][f4+2] = o.z; Os[bo][f4+3] = o.w;
        }
        __syncthreads();
#pragma unroll 8
        for (int fi = 0; fi < 128; fi++) {
            float w = Ws[c][fi];
            acc0 = fmaf(Os[bb][fi],     w, acc0);
            acc1 = fmaf(Os[bb + 4][fi], w, acc1);
        }
        __syncthreads();
    }
    atomicAdd(&out[bb * NCLASS + c],       acc0);
    atomicAdd(&out[(bb + 4) * NCLASS + c], acc1);
}

// ============================================================================
extern "C" void kernel_launch(void* const* d_in, const int* in_sizes, int n_in,
                              void* d_out, int out_size)
{
    const float* X  = (const float*)d_in[0];
    const float* Wq = (const float*)d_in[7];
    const float* Wk = (const float*)d_in[8];
    const float* Wv = (const float*)d_in[9];
    const float* Wa = (const float*)d_in[10];
    const float* bA = (const float*)d_in[11];
    const float* Wf = (const float*)d_in[12];
    const float* bF = (const float*)d_in[13];
    const float* rf = (const float*)d_in[14];
    float* out = (float*)d_out;

    static bool attr_done = false;
    if (!attr_done) {
        cudaFuncSetAttribute(k_proj_mma, cudaFuncAttributeMaxDynamicSharedMemorySize, SMEM_DYN2);
        cudaFuncSetAttribute(k_phi_mma,  cudaFuncAttributeMaxDynamicSharedMemorySize, SMEM_DYN2);
        attr_done = true;
    }

    k_cvt     <<<CVT_BLOCKS,      256>>>(X, Wq, Wk, Wv, Wa, rf, out, bF);
    k_proj_mma<<<dim3(8, 128),    256, SMEM_DYN2>>>();
    k_phi_mma <<<dim3(2, 128, 2), 256, SMEM_DYN2>>>();
    k_kv_mma  <<<dim3(4, 4, 8 * LSPLIT), 256>>>();
    k_num_mma <<<dim3(4, 16, 8),  256>>>(bA);
    k_final   <<<512, 256>>>(Wf, out);
}

// round 16
// speedup vs baseline: 1.0228x; 1.0228x over previous
#include <cuda_runtime.h>
#include <cuda_bf16.h>
#include <math.h>
#include <cstdint>

// Problem constants
#define NB     8
#define LSEQ   2048
#define BL     16384          // NB*LSEQ
#define DLEN   512
#define DM     256
#define NPROJ  1024           // Q|K|V|Add concatenated
#define MRF    256
#define TWOM   512
#define NCLASS 64
#define FTOT   (LSEQ*DM)      // 524288 flattened features per batch

#define TWO_PI 6.28318530717958647692f
#define LSPLIT 4              // L-splits for kv kernel

// ---------------- device scratch (allocation-free rule: static globals) ----
__device__ float g_qkva[BL * NPROJ];      // 64 MB : [row,1024]; only V|Add written
__device__ float g_ssq[2 * BL];           // fused row sum-of-squares (Q then K)
__device__ float g_qp[BL * TWOM];         // 32 MB (fp32 — num reads it)
__device__ float g_ksum[NB * TWOM];
__device__ float g_kv[NB * TWOM * DM];    // 4 MB
__device__ float g_out[BL * DM];          // 16 MB

// bf16 hi/lo split tensors
__device__ __nv_bfloat16 g_x_hi[BL * DLEN],  g_x_lo[BL * DLEN];     // 16+16 MB
__device__ __nv_bfloat16 g_w_hi[1024 * DLEN], g_w_lo[1024 * DLEN];  // 1+1 MB
__device__ __nv_bfloat16 g_rf_hi[MRF * MRF],  g_rf_lo[MRF * MRF];
__device__ __nv_bfloat16 g_qk_hi[BL * 512],  g_qk_lo[BL * 512];     // [row][Q|K]
__device__ __nv_bfloat16 g_kp_hi[BL * TWOM], g_kp_lo[BL * TWOM];    // phi(k), 16+16 MB

// ============================================================================
// helpers
// ============================================================================
__device__ __forceinline__ uint32_t smem_u32(const void* p) {
    uint32_t a;
    asm("{ .reg .u64 t; cvta.to.shared.u64 t, %1; cvt.u32.u64 %0, t; }" : "=r"(a) : "l"(p));
    return a;
}
__device__ __forceinline__ void ldmx4(uint32_t r[4], const void* p) {
    uint32_t a = smem_u32(p);
    asm volatile("ldmatrix.sync.aligned.m8n8.x4.shared.b16 {%0,%1,%2,%3}, [%4];"
                 : "=r"(r[0]), "=r"(r[1]), "=r"(r[2]), "=r"(r[3]) : "r"(a));
}
__device__ __forceinline__ void ldmx4t(uint32_t r[4], const void* p) {
    uint32_t a = smem_u32(p);
    asm volatile("ldmatrix.sync.aligned.m8n8.x4.trans.shared.b16 {%0,%1,%2,%3}, [%4];"
                 : "=r"(r[0]), "=r"(r[1]), "=r"(r[2]), "=r"(r[3]) : "r"(a));
}
__device__ __forceinline__ void mma16816(float d[4], const uint32_t a[4],
                                         uint32_t b0, uint32_t b1) {
    asm volatile(
        "mma.sync.aligned.m16n8k16.row.col.f32.bf16.bf16.f32 "
        "{%0,%1,%2,%3}, {%4,%5,%6,%7}, {%8,%9}, {%0,%1,%2,%3};"
        : "+f"(d[0]), "+f"(d[1]), "+f"(d[2]), "+f"(d[3])
        : "r"(a[0]), "r"(a[1]), "r"(a[2]), "r"(a[3]), "r"(b0), "r"(b1));
}
#define CP16(dst, src) asm volatile("cp.async.cg.shared.global [%0], [%1], 16;" :: "r"(dst), "l"(src))
#define CP_COMMIT()    asm volatile("cp.async.commit_group;" ::: "memory")
#define CP_WAIT1()     asm volatile("cp.async.wait_group 1;" ::: "memory")
#define CP_WAIT0()     asm volatile("cp.async.wait_group 0;" ::: "memory")

#define TPAD 40
#define KTP  136
#define KTPB 72

// Fast hi/lo split: packed bf16x2 converter + bit-level re-widen.
// Numerics identical to per-scalar __float2bfloat16_rn path.
__device__ __forceinline__ uint32_t pack_hl(float v0, float v1, uint32_t& lo_out) {
    uint32_t hi;
    asm("cvt.rn.bf16x2.f32 %0, %1, %2;" : "=r"(hi) : "f"(v1), "f"(v0));
    float h0 = __uint_as_float(hi << 16);
    float h1 = __uint_as_float(hi & 0xFFFF0000u);
    asm("cvt.rn.bf16x2.f32 %0, %1, %2;" : "=r"(lo_out) : "f"(v1 - h1), "f"(v0 - h0));
    return hi;
}
__device__ __forceinline__ void cvt8(const float xs[8], uint32_t hw[4], uint32_t lw[4]) {
#pragma unroll
    for (int q = 0; q < 4; q++)
        hw[q] = pack_hl(xs[2*q], xs[2*q+1], lw[q]);
}
__device__ __forceinline__ void stage8_cvt(const float* __restrict__ p,
                                           __nv_bfloat16* __restrict__ hi,
                                           __nv_bfloat16* __restrict__ lo,
                                           int idx) {
    float4 u = *(const float4*)p;
    float4 v = *(const float4*)(p + 4);
    float xs[8] = {u.x, u.y, u.z, u.w, v.x, v.y, v.z, v.w};
    uint32_t hw[4], lw[4];
    cvt8(xs, hw, lw);
    *(uint4*)(hi + idx) = make_uint4(hw[0], hw[1], hw[2], hw[3]);
    *(uint4*)(lo + idx) = make_uint4(lw[0], lw[1], lw[2], lw[3]);
}
__device__ __forceinline__ float bf_sum2(uint32_t w) {
    return __uint_as_float(w << 16) + __uint_as_float(w & 0xFFFF0000u);
}

// ============================================================================
// cp.async ping-pong GEMM core (128x128, NT): 8 warps 2x4, warp 64x32.
// ============================================================================
#define ST2_AHI 0
#define ST2_ALO (128 * TPAD)
#define ST2_BHI (2 * 128 * TPAD)
#define ST2_BLO (3 * 128 * TPAD)
#define ST2_SZ  (4 * 128 * TPAD)
#define SMEM_DYN2 (2 * ST2_SZ * 2)

template<int KCH>
__device__ __forceinline__ void gemm_core_cp2(
    const __nv_bfloat16* __restrict__ Ahi, const __nv_bfloat16* __restrict__ Alo, int astr,
    const __nv_bfloat16* __restrict__ Bhi, const __nv_bfloat16* __restrict__ Blo, int bstr,
    float acc[4][4][4], __nv_bfloat16* sm)
{
    const int tid = threadIdx.x, wid = tid >> 5, lane = tid & 31;
    const int wm = (wid >> 2) * 64, wn = (wid & 3) * 32;
    const int arow = wm + (lane & 15), akc = (lane >> 4) * 8;
    const int brow = wn + (lane >> 4) * 8 + (lane & 7), bkc = ((lane >> 3) & 1) * 8;

    const int rT = tid >> 1, cT = (tid & 1) * 2;

    auto issue = [&](int st, int k0) {
        __nv_bfloat16* base = sm + st * ST2_SZ;
#pragma unroll
        for (int j = 0; j < 2; j++) {
            int c = cT + j;
            CP16(smem_u32(base + ST2_AHI + rT * TPAD + c * 8), Ahi + (size_t)rT * astr + k0 + c * 8);
            CP16(smem_u32(base + ST2_ALO + rT * TPAD + c * 8), Alo + (size_t)rT * astr + k0 + c * 8);
            CP16(smem_u32(base + ST2_BHI + rT * TPAD + c * 8), Bhi + (size_t)rT * bstr + k0 + c * 8);
            CP16(smem_u32(base + ST2_BLO + rT * TPAD + c * 8), Blo + (size_t)rT * bstr + k0 + c * 8);
        }
        CP_COMMIT();
    };

    issue(0, 0);
    for (int ch = 0; ch < KCH; ch++) {
        if (ch + 1 < KCH) { issue((ch + 1) & 1, (ch + 1) * 32); CP_WAIT1(); }
        else              { CP_WAIT0(); }
        __syncthreads();

        const __nv_bfloat16* base = sm + (ch & 1) * ST2_SZ;
#pragma unroll
        for (int ks = 0; ks < 2; ks++) {
            const int kc = ks * 16;
            uint32_t ahi[4][4], alo[4][4];
#pragma unroll
            for (int mi = 0; mi < 4; mi++) {
                const int off = (arow + mi * 16) * TPAD + kc + akc;
                ldmx4(ahi[mi], base + ST2_AHI + off);
                ldmx4(alo[mi], base + ST2_ALO + off);
            }
            uint32_t bh[2][4], bl[2][4];
#pragma unroll
            for (int np = 0; np < 2; np++) {
                const int off = (brow + np * 16) * TPAD + kc + bkc;
                ldmx4(bh[np], base + ST2_BHI + off);
                ldmx4(bl[np], base + ST2_BLO + off);
            }
#pragma unroll
            for (int mi = 0; mi < 4; mi++)
#pragma unroll
                for (int nj = 0; nj < 4; nj++) {
                    const int np = nj >> 1, o = (nj & 1) * 2;
                    mma16816(acc[mi][nj], ahi[mi], bh[np][o], bh[np][o+1]);
                    mma16816(acc[mi][nj], ahi[mi], bl[np][o], bl[np][o+1]);
                    mma16816(acc[mi][nj], alo[mi], bh[np][o], bh[np][o+1]);
                }
        }
        __syncthreads();
    }
}

// ============================================================================
// Kernel -1: convert inputs + fused zero/init duties.
// ============================================================================
#define NXE (BL * DLEN)
#define NWE (1024 * DLEN)
#define NRE (MRF * MRF)
#define CVT_BLOCKS ((NXE + NWE + NRE) / 8 / 256)

__global__ void k_cvt(const float* __restrict__ X,
                      const float* __restrict__ Wq, const float* __restrict__ Wk,
                      const float* __restrict__ Wv, const float* __restrict__ Wa,
                      const float* __restrict__ rf,
                      float* __restrict__ out, const float* __restrict__ bf)
{
    int idx = blockIdx.x * 256 + threadIdx.x;
    if (idx < NB * TWOM * DM / 4)
        ((float4*)g_kv)[idx] = make_float4(0.f, 0.f, 0.f, 0.f);
    if (idx < 2 * BL / 4)
        ((float4*)g_ssq)[idx] = make_float4(0.f, 0.f, 0.f, 0.f);
    if (idx < NB * TWOM / 4)
        ((float4*)g_ksum)[idx] = make_float4(0.f, 0.f, 0.f, 0.f);
    if (idx < NB * NCLASS)
        out[idx] = bf[idx & 63];

    size_t base = ((size_t)blockIdx.x * 256 + threadIdx.x) * 8;
    const float* src;
    __nv_bfloat16 *dhi, *dlo;
    if (base < NXE) {
        src = X + base; dhi = g_x_hi + base; dlo = g_x_lo + base;
    } else if (base < NXE + NWE) {
        size_t off = base - NXE;
        int sel = (int)(off >> 17);
        const float* W = (sel == 0) ? Wq : (sel == 1) ? Wk : (sel == 2) ? Wv : Wa;
        src = W + (off & 131071); dhi = g_w_hi + off; dlo = g_w_lo + off;
    } else {
        size_t off = base - NXE - NWE;
        src = rf + off; dhi = g_rf_hi + off; dlo = g_rf_lo + off;
    }
    float4 u = *(const float4*)src, v = *(const float4*)(src + 4);
    float xs[8] = {u.x, u.y, u.z, u.w, v.x, v.y, v.z, v.w};
    uint32_t hw[4], lw[4];
    cvt8(xs, hw, lw);
    *(uint4*)dhi = make_uint4(hw[0], hw[1], hw[2], hw[3]);
    *(uint4*)dlo = make_uint4(lw[0], lw[1], lw[2], lw[3]);
}

// ============================================================================
// Kernel 1: proj (128x128 tiles). bn 0..3: Q|K bf16 hi/lo + fused ssq;
// bn 4..7: V|Add fp32.
// ============================================================================
__global__ void __launch_bounds__(256, 2) k_proj_mma()
{
    extern __shared__ __nv_bfloat16 sm[];
    const int bn = blockIdx.x;            // 0..7
    const int bm = blockIdx.y;            // 0..127

    const __nv_bfloat16* Ah = g_x_hi + (size_t)bm * 128 * DLEN;
    const __nv_bfloat16* Al = g_x_lo + (size_t)bm * 128 * DLEN;
    const __nv_bfloat16* Bh = g_w_hi + (size_t)bn * 128 * DLEN;
    const __nv_bfloat16* Bl = g_w_lo + (size_t)bn * 128 * DLEN;

    float acc[4][4][4] = {};
    gemm_core_cp2<16>(Ah, Al, DLEN, Bh, Bl, DLEN, acc, sm);

    const int tid = threadIdx.x, wid = tid >> 5, lane = tid & 31;
    const int r0 = bm * 128 + (wid >> 2) * 64 + (lane >> 2);
    const int c0 = bn * 128 + (wid & 3) * 32 + (lane & 3) * 2;

    if (bn < 4) {   // Q|K -> bf16 hi/lo + fused row sum-of-squares
        const int isK = bn >> 1;
#pragma unroll
        for (int mi = 0; mi < 4; mi++)
#pragma unroll
            for (int h = 0; h < 2; h++) {
                int r = r0 + mi * 16 + h * 8;
                float ss = 0.f;
#pragma unroll
                for (int nj = 0; nj < 4; nj++) {
                    int c = c0 + nj * 8;
                    float v0 = acc[mi][nj][h*2], v1 = acc[mi][nj][h*2+1];
                    ss = fmaf(v0, v0, ss);
                    ss = fmaf(v1, v1, ss);
                    uint32_t lo, hi = pack_hl(v0, v1, lo);
                    size_t idx = (size_t)r * 512 + c;
                    *(uint32_t*)(g_qk_hi + idx) = hi;
                    *(uint32_t*)(g_qk_lo + idx) = lo;
                }
                ss += __shfl_xor_sync(0xFFFFFFFFu, ss, 1);
                ss += __shfl_xor_sync(0xFFFFFFFFu, ss, 2);
                if ((lane & 3) == 0)
                    atomicAdd(&g_ssq[isK * BL + r], ss);
            }
    } else {        // V|Add -> fp32 qkva, cols 512..1023
#pragma unroll
        for (int mi = 0; mi < 4; mi++)
#pragma unroll
            for (int nj = 0; nj < 4; nj++) {
                int r = r0 + mi * 16, c = c0 + nj * 8;
                *(float2*)&g_qkva[(size_t)r * NPROJ + c]       = make_float2(acc[mi][nj][0], acc[mi][nj][1]);
                *(float2*)&g_qkva[(size_t)(r + 8) * NPROJ + c] = make_float2(acc[mi][nj][2], acc[mi][nj][3]);
            }
    }
}

// ============================================================================
// Kernel 3: phi. isQ -> fp32 g_qp; isK -> bf16 hi/lo g_kp_hi/lo.
// Inline expscale.
// ============================================================================
__global__ void __launch_bounds__(256, 2) k_phi_mma()
{
    extern __shared__ __nv_bfloat16 sm[];
    const int bn = blockIdx.x;            // 0..1
    const int bm = blockIdx.y;            // 0..127
    const int isK = blockIdx.z;

    const __nv_bfloat16* Ah = g_qk_hi + (size_t)bm * 128 * 512 + (isK ? DM : 0);
    const __nv_bfloat16* Al = g_qk_lo + (size_t)bm * 128 * 512 + (isK ? DM : 0);
    const __nv_bfloat16* Bh = g_rf_hi + (size_t)bn * 128 * MRF;
    const __nv_bfloat16* Bl = g_rf_lo + (size_t)bn * 128 * MRF;

    float acc[4][4][4] = {};
    gemm_core_cp2<8>(Ah, Al, 512, Bh, Bl, MRF, acc, sm);

    const float* SQ = g_ssq + isK * BL;

    const int tid = threadIdx.x, wid = tid >> 5, lane = tid & 31;
    const int r0 = bm * 128 + (wid >> 2) * 64 + (lane >> 2);
    const int c0 = bn * 128 + (wid & 3) * 32 + (lane & 3) * 2;   // feature 0..255
#pragma unroll
    for (int mi = 0; mi < 4; mi++) {
        int r = r0 + mi * 16;
        float sa = expf(0.5f * SQ[r])     * 0.0625f;
        float sb = expf(0.5f * SQ[r + 8]) * 0.0625f;
#pragma unroll
        for (int nj = 0; nj < 4; nj++) {
            int c = c0 + nj * 8;
            float s0, cz0, s1, cz1, s2, cz2, s3, cz3;
            sincosf(TWO_PI * acc[mi][nj][0], &s0, &cz0);
            sincosf(TWO_PI * acc[mi][nj][1], &s1, &cz1);
            sincosf(TWO_PI * acc[mi][nj][2], &s2, &cz2);
            sincosf(TWO_PI * acc[mi][nj][3], &s3, &cz3);
            float a0 = s0 * sa,  a1 = s1 * sa,  e0 = cz0 * sa, e1 = cz1 * sa;
            float b0 = s2 * sb,  b1 = s3 * sb,  f0 = cz2 * sb, f1 = cz3 * sb;
            if (isK) {
                uint32_t lo, hi;
                size_t ia = (size_t)r * TWOM + c;
                hi = pack_hl(a0, a1, lo);
                *(uint32_t*)(g_kp_hi + ia) = hi; *(uint32_t*)(g_kp_lo + ia) = lo;
                hi = pack_hl(e0, e1, lo);
                *(uint32_t*)(g_kp_hi + ia + DM) = hi; *(uint32_t*)(g_kp_lo + ia + DM) = lo;
                size_t ib = (size_t)(r + 8) * TWOM + c;
                hi = pack_hl(b0, b1, lo);
                *(uint32_t*)(g_kp_hi + ib) = hi; *(uint32_t*)(g_kp_lo + ib) = lo;
                hi = pack_hl(f0, f1, lo);
                *(uint32_t*)(g_kp_hi + ib + DM) = hi; *(uint32_t*)(g_kp_lo + ib + DM) = lo;
            } else {
                float* rowa = g_qp + (size_t)r * TWOM;
                float* rowb = g_qp + (size_t)(r + 8) * TWOM;
                *(float2*)&rowa[c]      = make_float2(a0, a1);
                *(float2*)&rowa[c + DM] = make_float2(e0, e1);
                *(float2*)&rowb[c]      = make_float2(b0, b1);
                *(float2*)&rowb[c + DM] = make_float2(f0, f1);
            }
        }
    }
}

// ============================================================================
// Kernel 4: kv. A = kp bf16 hi/lo via cp.async ping-pong (trans);
// B = v fp32 register-prefetch cvt8 (trans). Fused ksum from A fragments.
// ============================================================================
#define KVA_STG (2 * 32 * KTP)     // one stage: hi + lo

__global__ void __launch_bounds__(256, 2) k_kv_mma()
{
    __shared__ __nv_bfloat16 sA[2 * KVA_STG];              // ping-pong A
    __shared__ __nv_bfloat16 sBhi[32 * KTPB], sBlo[32 * KTPB];

    const int d0 = blockIdx.x * 64;
    const int m0 = blockIdx.y * 128;
    const int b  = blockIdx.z >> 2;
    const int sp = blockIdx.z & 3;
    const size_t rowb = (size_t)b * LSEQ;
    const float* vb = g_qkva + rowb * NPROJ + 2 * DM + d0;

    const int tid = threadIdx.x, wid = tid >> 5, lane = tid & 31;
    const int g8 = lane >> 3, r8 = lane & 7;
    const int wm = (wid >> 2) * 64, wn = (wid & 3) * 16;

    float acc[4][2][4] = {};
    float ksm[4][2] = {};

    const int rA = tid >> 3, cA = tid & 7;
    const int brow0 = tid >> 3, bcol8 = (tid & 7) * 8;

    auto issueA = [&](int st, int l0) {
        __nv_bfloat16* base = sA + st * KVA_STG;
        size_t src = (rowb + l0 + rA) * TWOM + m0;
#pragma unroll
        for (int j = 0; j < 2; j++) {
            int c = cA + j * 8;
            CP16(smem_u32(base + rA * KTP + c * 8),            g_kp_hi + src + c * 8);
            CP16(smem_u32(base + 32 * KTP + rA * KTP + c * 8), g_kp_lo + src + c * 8);
        }
        CP_COMMIT();
    };

    const int ch0 = sp * (LSEQ / 32 / LSPLIT);
    const int nch = LSEQ / 32 / LSPLIT;

    issueA(0, ch0 * 32);
    float pb[8];
    {
        const float* q = vb + (size_t)(ch0 * 32 + brow0) * NPROJ + bcol8;
        *(float4*)&pb[0] = *(const float4*)q;
        *(float4*)&pb[4] = *(const float4*)(q + 4);
    }

    for (int i = 0; i < nch; i++) {
        {   // store B from prefetched registers
            uint32_t hw[4], lw[4];
            cvt8(pb, hw, lw);
            int idx = brow0 * KTPB + bcol8;
            *(uint4*)(sBhi + idx) = make_uint4(hw[0], hw[1], hw[2], hw[3]);
            *(uint4*)(sBlo + idx) = make_uint4(lw[0], lw[1], lw[2], lw[3]);
        }
        if (i + 1 < nch) { issueA((i + 1) & 1, (ch0 + i + 1) * 32); CP_WAIT1(); }
        else             { CP_WAIT0(); }
        __syncthreads();

        if (i + 1 < nch) {   // prefetch next B (overlaps MMA)
            const float* q = vb + (size_t)((ch0 + i + 1) * 32 + brow0) * NPROJ + bcol8;
            *(float4*)&pb[0] = *(const float4*)q;
            *(float4*)&pb[4] = *(const float4*)(q + 4);
        }

        const __nv_bfloat16* baseA = sA + (i & 1) * KVA_STG;
#pragma unroll
        for (int ks = 0; ks < 2; ks++) {
            const int kc = ks * 16;
            uint32_t ahi[4][4], alo[4][4];
#pragma unroll
            for (int mi = 0; mi < 4; mi++) {
                const int off = (kc + r8 + (g8 >> 1) * 8) * KTP + wm + mi * 16 + (g8 & 1) * 8;
                ldmx4t(ahi[mi], baseA + off);
                ldmx4t(alo[mi], baseA + 32 * KTP + off);
            }
            uint32_t bhi[4], blo[4];
            {
                const int off = (kc + r8 + (g8 & 1) * 8) * KTPB + wn + (g8 >> 1) * 8;
                ldmx4t(bhi, sBhi + off);
                ldmx4t(blo, sBlo + off);
            }
#pragma unroll
            for (int mi = 0; mi < 4; mi++)
#pragma unroll
                for (int nj = 0; nj < 2; nj++) {
                    const int o = nj * 2;
                    mma16816(acc[mi][nj], ahi[mi], bhi[o], bhi[o+1]);
                    mma16816(acc[mi][nj], ahi[mi], blo[o], blo[o+1]);
                    mma16816(acc[mi][nj], alo[mi], bhi[o], bhi[o+1]);
                }
            if (blockIdx.x == 0 && wn == 0) {   // fused ksum from A fragments
#pragma unroll
                for (int mi = 0; mi < 4; mi++) {
                    ksm[mi][0] += bf_sum2(ahi[mi][0]) + bf_sum2(ahi[mi][2])
                                + bf_sum2(alo[mi][0]) + bf_sum2(alo[mi][2]);
                    ksm[mi][1] += bf_sum2(ahi[mi][1]) + bf_sum2(ahi[mi][3])
                                + bf_sum2(alo[mi][1]) + bf_sum2(alo[mi][3]);
                }
            }
        }
        __syncthreads();
    }

    const int rr0 = m0 + wm + (lane >> 2);
    const int cc0 = d0 + wn + (lane & 3) * 2;
#pragma unroll
    for (int mi = 0; mi < 4; mi++)
#pragma unroll
        for (int nj = 0; nj < 2; nj++) {
            int r = rr0 + mi * 16, c = cc0 + nj * 8;
            float* p0 = &g_kv[((size_t)b * TWOM + r) * DM + c];
            float* p1 = &g_kv[((size_t)b * TWOM + r + 8) * DM + c];
            atomicAdd(p0,     acc[mi][nj][0]);
            atomicAdd(p0 + 1, acc[mi][nj][1]);
            atomicAdd(p1,     acc[mi][nj][2]);
            atomicAdd(p1 + 1, acc[mi][nj][3]);
        }

    if (blockIdx.x == 0 && wn == 0) {
#pragma unroll
        for (int mi = 0; mi < 4; mi++) {
            float s0 = ksm[mi][0], s1 = ksm[mi][1];
            s0 += __shfl_xor_sync(0xFFFFFFFFu, s0, 1);
            s0 += __shfl_xor_sync(0xFFFFFFFFu, s0, 2);
            s1 += __shfl_xor_sync(0xFFFFFFFFu, s1, 1);
            s1 += __shfl_xor_sync(0xFFFFFFFFu, s1, 2);
            if ((lane & 3) == 0) {
                int m = m0 + wm + mi * 16 + (lane >> 2);
                atomicAdd(&g_ksum[b * TWOM + m],     s0);
                atomicAdd(&g_ksum[b * TWOM + m + 8], s1);
            }
        }
    }
}

// ============================================================================
// Kernel 5 (mma): num + fused denom + epilogue  (reads fp32 qp/kv)
// ============================================================================
__global__ void __launch_bounds__(256, 2) k_num_mma(const float* __restrict__ b_add)
{
    __shared__ __nv_bfloat16 sAhi[128 * TPAD], sAlo[128 * TPAD];
    __shared__ __nv_bfloat16 sBhi[32 * KTPB],  sBlo[32 * KTPB];
    __shared__ float red2[128][4];

    const int d0 = blockIdx.x * 64;
    const int lt = blockIdx.y * 128;
    const int b  = blockIdx.z;
    const float* qpb = g_qp + (size_t)(b * LSEQ + lt) * TWOM;
    const float* kvb = g_kv + (size_t)b * TWOM * DM + d0;
    const float* ksb = g_ksum + b * TWOM;

    const int tid = threadIdx.x, wid = tid >> 5, lane = tid & 31;
    const int g8 = lane >> 3, r8 = lane & 7;
    const int wm = (wid >> 2) * 64, wn = (wid & 3) * 16;
    const int arow = wm + (lane & 15);
    const int akc  = (lane >> 4) * 8;

    float acc[4][2][4] = {};
    float dn[2] = {0.f, 0.f};

    const int srow0 = tid >> 2, scol8 = (tid & 3) * 8;
    const int brow0 = tid >> 3, bcol8 = (tid & 7) * 8;

    float pa[2][8], pb[8];
#pragma unroll
    for (int i = 0; i < 2; i++) {
        const float* p = qpb + (size_t)(srow0 + i * 64) * TWOM + scol8;
        *(float4*)&pa[i][0] = *(const float4*)p;
        *(float4*)&pa[i][4] = *(const float4*)(p + 4);
    }
    {
        const float* q = kvb + (size_t)brow0 * DM + bcol8;
        *(float4*)&pb[0] = *(const float4*)q;
        *(float4*)&pb[4] = *(const float4*)(q + 4);
    }

    for (int ch = 0; ch < TWOM / 32; ch++) {
        const int k0 = ch * 32;
#pragma unroll
        for (int i = 0; i < 2; i++) {
            int row = srow0 + i * 64;
            uint32_t hw[4], lw[4];
            cvt8(pa[i], hw, lw);
            const float* ks = ksb + k0 + scol8;
#pragma unroll
            for (int q = 0; q < 8; q++) dn[i] = fmaf(pa[i][q], ks[q], dn[i]);
            *(uint4*)(sAhi + row * TPAD + scol8) = make_uint4(hw[0], hw[1], hw[2], hw[3]);
            *(uint4*)(sAlo + row * TPAD + scol8) = make_uint4(lw[0], lw[1], lw[2], lw[3]);
        }
        {
            uint32_t hw[4], lw[4];
            cvt8(pb, hw, lw);
            int idx = brow0 * KTPB + bcol8;
            *(uint4*)(sBhi + idx) = make_uint4(hw[0], hw[1], hw[2], hw[3]);
            *(uint4*)(sBlo + idx) = make_uint4(lw[0], lw[1], lw[2], lw[3]);
        }
        __syncthreads();

        if (ch + 1 < TWOM / 32) {
            const int k1 = (ch + 1) * 32;
#pragma unroll
            for (int i = 0; i < 2; i++) {
                const float* p = qpb + (size_t)(srow0 + i * 64) * TWOM + k1 + scol8;
                *(float4*)&pa[i][0] = *(const float4*)p;
                *(float4*)&pa[i][4] = *(const float4*)(p + 4);
            }
            const float* q = kvb + (size_t)(k1 + brow0) * DM + bcol8;
            *(float4*)&pb[0] = *(const float4*)q;
            *(float4*)&pb[4] = *(const float4*)(q + 4);
        }

#pragma unroll
        for (int ks2 = 0; ks2 < 2; ks2++) {
            const int kc = ks2 * 16;
            uint32_t ahi[4][4], alo[4][4];
#pragma unroll
            for (int mi = 0; mi < 4; mi++) {
                const int off = (arow + mi * 16) * TPAD + kc + akc;
                ldmx4(ahi[mi], sAhi + off);
                ldmx4(alo[mi], sAlo + off);
            }
            uint32_t bhi[4], blo[4];
            {
                const int off = (kc + r8 + (g8 & 1) * 8) * KTPB + wn + (g8 >> 1) * 8;
                ldmx4t(bhi, sBhi + off);
                ldmx4t(blo, sBlo + off);
            }
#pragma unroll
            for (int mi = 0; mi < 4; mi++)
#pragma unroll
                for (int nj = 0; nj < 2; nj++) {
                    const int o = nj * 2;
                    mma16816(acc[mi][nj], ahi[mi], bhi[o], bhi[o+1]);
                    mma16816(acc[mi][nj], ahi[mi], blo[o], blo[o+1]);
                    mma16816(acc[mi][nj], alo[mi], bhi[o], bhi[o+1]);
                }
        }
        __syncthreads();
    }

    red2[srow0][tid & 3]      = dn[0];
    red2[srow0 + 64][tid & 3] = dn[1];
    __syncthreads();

    const int rr0 = wm + (lane >> 2);
    const int cc0 = d0 + wn + (lane & 3) * 2;
#pragma unroll
    for (int mi = 0; mi < 4; mi++) {
#pragma unroll
        for (int h = 0; h < 2; h++) {
            int rloc = rr0 + mi * 16 + h * 8;
            float den = red2[rloc][0] + red2[rloc][1] + red2[rloc][2] + red2[rloc][3];
            float inv = 1.0f / den;
            int rg = b * LSEQ + lt + rloc;
            const float* addp = g_qkva + (size_t)rg * NPROJ + 3 * DM;
            float* orow = g_out + (size_t)rg * DM;
#pragma unroll
            for (int nj = 0; nj < 2; nj++) {
                int c = cc0 + nj * 8;
                float v0 = acc[mi][nj][h*2]   * inv + addp[c]     + b_add[c];
                float v1 = acc[mi][nj][h*2+1] * inv + addp[c + 1] + b_add[c + 1];
                *(float2*)&orow[c] = make_float2(v0, v1);
            }
        }
    }
}

// ============================================================================
// Kernel 6: final GEMM (split-K atomics; out pre-seeded with b_final by k_cvt)
// ============================================================================
__global__ void __launch_bounds__(256) k_final(const float* __restrict__ Wf,
                                               float* __restrict__ out)
{
    __shared__ float Ws[64][130];
    __shared__ float Os[8][132];

    const int tid = threadIdx.x;
    const int c  = tid & 63;
    const int bb = tid >> 6;
    float acc0 = 0.f, acc1 = 0.f;
    const int f0 = blockIdx.x * 1024;

    for (int t = 0; t < 1024; t += 128) {
        const int fbase = f0 + t;
#pragma unroll
        for (int i = 0; i < 8; i++) {
            int v = tid + i * 256;
            int cc = v >> 5, f4 = (v & 31) * 4;
            float4 w = *(const float4*)(Wf + (size_t)cc * FTOT + fbase + f4);
            Ws[cc][f4] = w.x; Ws[cc][f4+1] = w.y; Ws[cc][f4+2] = w.z; Ws[cc][f4+3] = w.w;
        }
        {
            int v = tid;
            int bo = v >> 5, f4 = (v & 31) * 4;
            float4 o = *(const float4*)(g_out + (size_t)bo * FTOT + fbase + f4);
            Os[bo][f4] = o.x; Os[bo][f4+1] = o.y; Os[bo][f4+2] = o.z; Os[bo][f4+3] = o.w;
        }
        __syncthreads();
#pragma unroll 8
        for (int fi = 0; fi < 128; fi++) {
            float w = Ws[c][fi];
            acc0 = fmaf(Os[bb][fi],     w, acc0);
            acc1 = fmaf(Os[bb + 4][fi], w, acc1);
        }
        __syncthreads();
    }
    atomicAdd(&out[bb * NCLASS + c],       acc0);
    atomicAdd(&out[(bb + 4) * NCLASS + c], acc1);
}

// ============================================================================
extern "C" void kernel_launch(void* const* d_in, const int* in_sizes, int n_in,
                              void* d_out, int out_size)
{
    const float* X  = (const float*)d_in[0];
    const float* Wq = (const float*)d_in[7];
    const float* Wk = (const float*)d_in[8];
    const float* Wv = (const float*)d_in[9];
    const float* Wa = (const float*)d_in[10];
    const float* bA = (const float*)d_in[11];
    const float* Wf = (const float*)d_in[12];
    const float* bF = (const float*)d_in[13];
    const float* rf = (const float*)d_in[14];
    float* out = (float*)d_out;

    static bool attr_done = false;
    if (!attr_done) {
        cudaFuncSetAttribute(k_proj_mma, cudaFuncAttributeMaxDynamicSharedMemorySize, SMEM_DYN2);
        cudaFuncSetAttribute(k_phi_mma,  cudaFuncAttributeMaxDynamicSharedMemorySize, SMEM_DYN2);
        attr_done = true;
    }

    k_cvt     <<<CVT_BLOCKS,      256>>>(X, Wq, Wk, Wv, Wa, rf, out, bF);
    k_proj_mma<<<dim3(8, 128),    256, SMEM_DYN2>>>();
    k_phi_mma <<<dim3(2, 128, 2), 256, SMEM_DYN2>>>();
    k_kv_mma  <<<dim3(4, 4, 8 * LSPLIT), 256>>>();
    k_num_mma <<<dim3(4, 16, 8),  256>>>(bA);
    k_final   <<<512, 256>>>(Wf, out);
}

// round 17
// speedup vs baseline: 1.0506x; 1.0272x over previous
#include <cuda_runtime.h>
#include <cuda_bf16.h>
#include <math.h>
#include <cstdint>

// Problem constants
#define NB     8
#define LSEQ   2048
#define BL     16384          // NB*LSEQ
#define DLEN   512
#define DM     256
#define NPROJ  1024           // Q|K|V|Add concatenated
#define MRF    256
#define TWOM   512
#define NCLASS 64
#define FTOT   (LSEQ*DM)      // 524288 flattened features per batch

#define TWO_PI 6.28318530717958647692f
#define LSPLIT 4              // L-splits for kv kernel

// ---------------- device scratch (allocation-free rule: static globals) ----
__device__ float g_qkva[BL * NPROJ];      // 64 MB : [row,1024]; only V|Add written
__device__ float g_ssq[2 * BL];           // fused row sum-of-squares (Q then K)
__device__ float g_qp[BL * TWOM];         // 32 MB (fp32 — num reads it)
__device__ float g_ksum[NB * TWOM];
__device__ float g_kv[NB * TWOM * DM];    // 4 MB
__device__ float g_out[BL * DM];          // 16 MB

// bf16 hi/lo split tensors
__device__ __nv_bfloat16 g_x_hi[BL * DLEN],  g_x_lo[BL * DLEN];     // 16+16 MB
__device__ __nv_bfloat16 g_w_hi[1024 * DLEN], g_w_lo[1024 * DLEN];  // 1+1 MB
__device__ __nv_bfloat16 g_rf_hi[MRF * MRF],  g_rf_lo[MRF * MRF];
__device__ __nv_bfloat16 g_qk_hi[BL * 512],  g_qk_lo[BL * 512];     // [row][Q|K]
__device__ __nv_bfloat16 g_kp_hi[BL * TWOM], g_kp_lo[BL * TWOM];    // phi(k), 16+16 MB

// ============================================================================
// helpers
// ============================================================================
__device__ __forceinline__ uint32_t smem_u32(const void* p) {
    uint32_t a;
    asm("{ .reg .u64 t; cvta.to.shared.u64 t, %1; cvt.u32.u64 %0, t; }" : "=r"(a) : "l"(p));
    return a;
}
__device__ __forceinline__ void ldmx4(uint32_t r[4], const void* p) {
    uint32_t a = smem_u32(p);
    asm volatile("ldmatrix.sync.aligned.m8n8.x4.shared.b16 {%0,%1,%2,%3}, [%4];"
                 : "=r"(r[0]), "=r"(r[1]), "=r"(r[2]), "=r"(r[3]) : "r"(a));
}
__device__ __forceinline__ void ldmx4t(uint32_t r[4], const void* p) {
    uint32_t a = smem_u32(p);
    asm volatile("ldmatrix.sync.aligned.m8n8.x4.trans.shared.b16 {%0,%1,%2,%3}, [%4];"
                 : "=r"(r[0]), "=r"(r[1]), "=r"(r[2]), "=r"(r[3]) : "r"(a));
}
__device__ __forceinline__ void mma16816(float d[4], const uint32_t a[4],
                                         uint32_t b0, uint32_t b1) {
    asm volatile(
        "mma.sync.aligned.m16n8k16.row.col.f32.bf16.bf16.f32 "
        "{%0,%1,%2,%3}, {%4,%5,%6,%7}, {%8,%9}, {%0,%1,%2,%3};"
        : "+f"(d[0]), "+f"(d[1]), "+f"(d[2]), "+f"(d[3])
        : "r"(a[0]), "r"(a[1]), "r"(a[2]), "r"(a[3]), "r"(b0), "r"(b1));
}
#define CP16(dst, src) asm volatile("cp.async.cg.shared.global [%0], [%1], 16;" :: "r"(dst), "l"(src))
#define CP_COMMIT()    asm volatile("cp.async.commit_group;" ::: "memory")
#define CP_WAIT1()     asm volatile("cp.async.wait_group 1;" ::: "memory")
#define CP_WAIT0()     asm volatile("cp.async.wait_group 0;" ::: "memory")

#define TPAD 40
#define KTP  136
#define KTPB 72

// Fast hi/lo split: packed bf16x2 converter + bit-level re-widen.
__device__ __forceinline__ uint32_t pack_hl(float v0, float v1, uint32_t& lo_out) {
    uint32_t hi;
    asm("cvt.rn.bf16x2.f32 %0, %1, %2;" : "=r"(hi) : "f"(v1), "f"(v0));
    float h0 = __uint_as_float(hi << 16);
    float h1 = __uint_as_float(hi & 0xFFFF0000u);
    asm("cvt.rn.bf16x2.f32 %0, %1, %2;" : "=r"(lo_out) : "f"(v1 - h1), "f"(v0 - h0));
    return hi;
}
__device__ __forceinline__ void cvt8(const float xs[8], uint32_t hw[4], uint32_t lw[4]) {
#pragma unroll
    for (int q = 0; q < 4; q++)
        hw[q] = pack_hl(xs[2*q], xs[2*q+1], lw[q]);
}
__device__ __forceinline__ float bf_sum2(uint32_t w) {
    return __uint_as_float(w << 16) + __uint_as_float(w & 0xFFFF0000u);
}

// ============================================================================
// cp.async ping-pong GEMM core (128x128, NT): 8 warps 2x4, warp 64x32.
// ============================================================================
#define ST2_AHI 0
#define ST2_ALO (128 * TPAD)
#define ST2_BHI (2 * 128 * TPAD)
#define ST2_BLO (3 * 128 * TPAD)
#define ST2_SZ  (4 * 128 * TPAD)
#define SMEM_DYN2 (2 * ST2_SZ * 2)

template<int KCH>
__device__ __forceinline__ void gemm_core_cp2(
    const __nv_bfloat16* __restrict__ Ahi, const __nv_bfloat16* __restrict__ Alo, int astr,
    const __nv_bfloat16* __restrict__ Bhi, const __nv_bfloat16* __restrict__ Blo, int bstr,
    float acc[4][4][4], __nv_bfloat16* sm)
{
    const int tid = threadIdx.x, wid = tid >> 5, lane = tid & 31;
    const int wm = (wid >> 2) * 64, wn = (wid & 3) * 32;
    const int arow = wm + (lane & 15), akc = (lane >> 4) * 8;
    const int brow = wn + (lane >> 4) * 8 + (lane & 7), bkc = ((lane >> 3) & 1) * 8;

    const int rT = tid >> 1, cT = (tid & 1) * 2;

    auto issue = [&](int st, int k0) {
        __nv_bfloat16* base = sm + st * ST2_SZ;
#pragma unroll
        for (int j = 0; j < 2; j++) {
            int c = cT + j;
            CP16(smem_u32(base + ST2_AHI + rT * TPAD + c * 8), Ahi + (size_t)rT * astr + k0 + c * 8);
            CP16(smem_u32(base + ST2_ALO + rT * TPAD + c * 8), Alo + (size_t)rT * astr + k0 + c * 8);
            CP16(smem_u32(base + ST2_BHI + rT * TPAD + c * 8), Bhi + (size_t)rT * bstr + k0 + c * 8);
            CP16(smem_u32(base + ST2_BLO + rT * TPAD + c * 8), Blo + (size_t)rT * bstr + k0 + c * 8);
        }
        CP_COMMIT();
    };

    issue(0, 0);
    for (int ch = 0; ch < KCH; ch++) {
        if (ch + 1 < KCH) { issue((ch + 1) & 1, (ch + 1) * 32); CP_WAIT1(); }
        else              { CP_WAIT0(); }
        __syncthreads();

        const __nv_bfloat16* base = sm + (ch & 1) * ST2_SZ;
#pragma unroll
        for (int ks = 0; ks < 2; ks++) {
            const int kc = ks * 16;
            uint32_t ahi[4][4], alo[4][4];
#pragma unroll
            for (int mi = 0; mi < 4; mi++) {
                const int off = (arow + mi * 16) * TPAD + kc + akc;
                ldmx4(ahi[mi], base + ST2_AHI + off);
                ldmx4(alo[mi], base + ST2_ALO + off);
            }
            uint32_t bh[2][4], bl[2][4];
#pragma unroll
            for (int np = 0; np < 2; np++) {
                const int off = (brow + np * 16) * TPAD + kc + bkc;
                ldmx4(bh[np], base + ST2_BHI + off);
                ldmx4(bl[np], base + ST2_BLO + off);
            }
#pragma unroll
            for (int mi = 0; mi < 4; mi++)
#pragma unroll
                for (int nj = 0; nj < 4; nj++) {
                    const int np = nj >> 1, o = (nj & 1) * 2;
                    mma16816(acc[mi][nj], ahi[mi], bh[np][o], bh[np][o+1]);
                    mma16816(acc[mi][nj], ahi[mi], bl[np][o], bl[np][o+1]);
                    mma16816(acc[mi][nj], alo[mi], bh[np][o], bh[np][o+1]);
                }
        }
        __syncthreads();
    }
}

// ============================================================================
// Kernel -1: convert inputs + fused zero/init duties.
// ============================================================================
#define NXE (BL * DLEN)
#define NWE (1024 * DLEN)
#define NRE (MRF * MRF)
#define CVT_BLOCKS ((NXE + NWE + NRE) / 8 / 256)

__global__ void k_cvt(const float* __restrict__ X,
                      const float* __restrict__ Wq, const float* __restrict__ Wk,
                      const float* __restrict__ Wv, const float* __restrict__ Wa,
                      const float* __restrict__ rf,
                      float* __restrict__ out, const float* __restrict__ bf)
{
    int idx = blockIdx.x * 256 + threadIdx.x;
    if (idx < NB * TWOM * DM / 4)
        ((float4*)g_kv)[idx] = make_float4(0.f, 0.f, 0.f, 0.f);
    if (idx < 2 * BL / 4)
        ((float4*)g_ssq)[idx] = make_float4(0.f, 0.f, 0.f, 0.f);
    if (idx < NB * TWOM / 4)
        ((float4*)g_ksum)[idx] = make_float4(0.f, 0.f, 0.f, 0.f);
    if (idx < NB * NCLASS)
        out[idx] = bf[idx & 63];

    size_t base = ((size_t)blockIdx.x * 256 + threadIdx.x) * 8;
    const float* src;
    __nv_bfloat16 *dhi, *dlo;
    if (base < NXE) {
        src = X + base; dhi = g_x_hi + base; dlo = g_x_lo + base;
    } else if (base < NXE + NWE) {
        size_t off = base - NXE;
        int sel = (int)(off >> 17);
        const float* W = (sel == 0) ? Wq : (sel == 1) ? Wk : (sel == 2) ? Wv : Wa;
        src = W + (off & 131071); dhi = g_w_hi + off; dlo = g_w_lo + off;
    } else {
        size_t off = base - NXE - NWE;
        src = rf + off; dhi = g_rf_hi + off; dlo = g_rf_lo + off;
    }
    float4 u = *(const float4*)src, v = *(const float4*)(src + 4);
    float xs[8] = {u.x, u.y, u.z, u.w, v.x, v.y, v.z, v.w};
    uint32_t hw[4], lw[4];
    cvt8(xs, hw, lw);
    *(uint4*)dhi = make_uint4(hw[0], hw[1], hw[2], hw[3]);
    *(uint4*)dlo = make_uint4(lw[0], lw[1], lw[2], lw[3]);
}

// ============================================================================
// Kernel 1: proj (128x128 tiles). bn 0..3: Q|K bf16 hi/lo + fused ssq;
// bn 4..7: V|Add fp32.
// ============================================================================
__global__ void __launch_bounds__(256, 2) k_proj_mma()
{
    extern __shared__ __nv_bfloat16 sm[];
    const int bn = blockIdx.x;            // 0..7
    const int bm = blockIdx.y;            // 0..127

    const __nv_bfloat16* Ah = g_x_hi + (size_t)bm * 128 * DLEN;
    const __nv_bfloat16* Al = g_x_lo + (size_t)bm * 128 * DLEN;
    const __nv_bfloat16* Bh = g_w_hi + (size_t)bn * 128 * DLEN;
    const __nv_bfloat16* Bl = g_w_lo + (size_t)bn * 128 * DLEN;

    float acc[4][4][4] = {};
    gemm_core_cp2<16>(Ah, Al, DLEN, Bh, Bl, DLEN, acc, sm);

    const int tid = threadIdx.x, wid = tid >> 5, lane = tid & 31;
    const int r0 = bm * 128 + (wid >> 2) * 64 + (lane >> 2);
    const int c0 = bn * 128 + (wid & 3) * 32 + (lane & 3) * 2;

    if (bn < 4) {   // Q|K -> bf16 hi/lo + fused row sum-of-squares
        const int isK = bn >> 1;
#pragma unroll
        for (int mi = 0; mi < 4; mi++)
#pragma unroll
            for (int h = 0; h < 2; h++) {
                int r = r0 + mi * 16 + h * 8;
                float ss = 0.f;
#pragma unroll
                for (int nj = 0; nj < 4; nj++) {
                    int c = c0 + nj * 8;
                    float v0 = acc[mi][nj][h*2], v1 = acc[mi][nj][h*2+1];
                    ss = fmaf(v0, v0, ss);
                    ss = fmaf(v1, v1, ss);
                    uint32_t lo, hi = pack_hl(v0, v1, lo);
                    size_t idx = (size_t)r * 512 + c;
                    *(uint32_t*)(g_qk_hi + idx) = hi;
                    *(uint32_t*)(g_qk_lo + idx) = lo;
                }
                ss += __shfl_xor_sync(0xFFFFFFFFu, ss, 1);
                ss += __shfl_xor_sync(0xFFFFFFFFu, ss, 2);
                if ((lane & 3) == 0)
                    atomicAdd(&g_ssq[isK * BL + r], ss);
            }
    } else {        // V|Add -> fp32 qkva, cols 512..1023
#pragma unroll
        for (int mi = 0; mi < 4; mi++)
#pragma unroll
            for (int nj = 0; nj < 4; nj++) {
                int r = r0 + mi * 16, c = c0 + nj * 8;
                *(float2*)&g_qkva[(size_t)r * NPROJ + c]       = make_float2(acc[mi][nj][0], acc[mi][nj][1]);
                *(float2*)&g_qkva[(size_t)(r + 8) * NPROJ + c] = make_float2(acc[mi][nj][2], acc[mi][nj][3]);
            }
    }
}

// ============================================================================
// Kernel 3: phi. isQ -> fp32 g_qp; isK -> bf16 hi/lo g_kp_hi/lo.
// Inline expscale.
// ============================================================================
__global__ void __launch_bounds__(256, 2) k_phi_mma()
{
    extern __shared__ __nv_bfloat16 sm[];
    const int bn = blockIdx.x;            // 0..1
    const int bm = blockIdx.y;            // 0..127
    const int isK = blockIdx.z;

    const __nv_bfloat16* Ah = g_qk_hi + (size_t)bm * 128 * 512 + (isK ? DM : 0);
    const __nv_bfloat16* Al = g_qk_lo + (size_t)bm * 128 * 512 + (isK ? DM : 0);
    const __nv_bfloat16* Bh = g_rf_hi + (size_t)bn * 128 * MRF;
    const __nv_bfloat16* Bl = g_rf_lo + (size_t)bn * 128 * MRF;

    float acc[4][4][4] = {};
    gemm_core_cp2<8>(Ah, Al, 512, Bh, Bl, MRF, acc, sm);

    const float* SQ = g_ssq + isK * BL;

    const int tid = threadIdx.x, wid = tid >> 5, lane = tid & 31;
    const int r0 = bm * 128 + (wid >> 2) * 64 + (lane >> 2);
    const int c0 = bn * 128 + (wid & 3) * 32 + (lane & 3) * 2;   // feature 0..255
#pragma unroll
    for (int mi = 0; mi < 4; mi++) {
        int r = r0 + mi * 16;
        float sa = expf(0.5f * SQ[r])     * 0.0625f;
        float sb = expf(0.5f * SQ[r + 8]) * 0.0625f;
#pragma unroll
        for (int nj = 0; nj < 4; nj++) {
            int c = c0 + nj * 8;
            float s0, cz0, s1, cz1, s2, cz2, s3, cz3;
            sincosf(TWO_PI * acc[mi][nj][0], &s0, &cz0);
            sincosf(TWO_PI * acc[mi][nj][1], &s1, &cz1);
            sincosf(TWO_PI * acc[mi][nj][2], &s2, &cz2);
            sincosf(TWO_PI * acc[mi][nj][3], &s3, &cz3);
            float a0 = s0 * sa,  a1 = s1 * sa,  e0 = cz0 * sa, e1 = cz1 * sa;
            float b0 = s2 * sb,  b1 = s3 * sb,  f0 = cz2 * sb, f1 = cz3 * sb;
            if (isK) {
                uint32_t lo, hi;
                size_t ia = (size_t)r * TWOM + c;
                hi = pack_hl(a0, a1, lo);
                *(uint32_t*)(g_kp_hi + ia) = hi; *(uint32_t*)(g_kp_lo + ia) = lo;
                hi = pack_hl(e0, e1, lo);
                *(uint32_t*)(g_kp_hi + ia + DM) = hi; *(uint32_t*)(g_kp_lo + ia + DM) = lo;
                size_t ib = (size_t)(r + 8) * TWOM + c;
                hi = pack_hl(b0, b1, lo);
                *(uint32_t*)(g_kp_hi + ib) = hi; *(uint32_t*)(g_kp_lo + ib) = lo;
                hi = pack_hl(f0, f1, lo);
                *(uint32_t*)(g_kp_hi + ib + DM) = hi; *(uint32_t*)(g_kp_lo + ib + DM) = lo;
            } else {
                float* rowa = g_qp + (size_t)r * TWOM;
                float* rowb = g_qp + (size_t)(r + 8) * TWOM;
                *(float2*)&rowa[c]      = make_float2(a0, a1);
                *(float2*)&rowa[c + DM] = make_float2(e0, e1);
                *(float2*)&rowb[c]      = make_float2(b0, b1);
                *(float2*)&rowb[c + DM] = make_float2(f0, f1);
            }
        }
    }
}

// ============================================================================
// Kernel 4: kv. A = kp bf16 hi/lo via cp.async ping-pong (trans);
// B = v fp32 register-prefetch cvt8 (trans). Warp grid 4(m)x2(n), tile 32x32.
// Fused ksum from A fragments. Atomic fp32 accumulate into g_kv.
// ============================================================================
#define KVA_STG (2 * 32 * KTP)     // one stage: hi + lo

__global__ void __launch_bounds__(256, 2) k_kv_mma()
{
    __shared__ __nv_bfloat16 sA[2 * KVA_STG];              // ping-pong A
    __shared__ __nv_bfloat16 sBhi[32 * KTPB], sBlo[32 * KTPB];

    const int d0 = blockIdx.x * 64;
    const int m0 = blockIdx.y * 128;
    const int b  = blockIdx.z >> 2;
    const int sp = blockIdx.z & 3;
    const size_t rowb = (size_t)b * LSEQ;
    const float* vb = g_qkva + rowb * NPROJ + 2 * DM + d0;

    const int tid = threadIdx.x, wid = tid >> 5, lane = tid & 31;
    const int g8 = lane >> 3, r8 = lane & 7;
    const int wm = (wid >> 1) * 32, wn = (wid & 1) * 32;   // 4x2 warp grid

    float acc[2][4][4] = {};
    float ksm[2][2] = {};

    const int rA = tid >> 3, cA = tid & 7;
    const int brow0 = tid >> 3, bcol8 = (tid & 7) * 8;

    auto issueA = [&](int st, int l0) {
        __nv_bfloat16* base = sA + st * KVA_STG;
        size_t src = (rowb + l0 + rA) * TWOM + m0;
#pragma unroll
        for (int j = 0; j < 2; j++) {
            int c = cA + j * 8;
            CP16(smem_u32(base + rA * KTP + c * 8),            g_kp_hi + src + c * 8);
            CP16(smem_u32(base + 32 * KTP + rA * KTP + c * 8), g_kp_lo + src + c * 8);
        }
        CP_COMMIT();
    };

    const int ch0 = sp * (LSEQ / 32 / LSPLIT);
    const int nch = LSEQ / 32 / LSPLIT;

    issueA(0, ch0 * 32);
    float pb[8];
    {
        const float* q = vb + (size_t)(ch0 * 32 + brow0) * NPROJ + bcol8;
        *(float4*)&pb[0] = *(const float4*)q;
        *(float4*)&pb[4] = *(const float4*)(q + 4);
    }

    for (int i = 0; i < nch; i++) {
        {   // store B from prefetched registers
            uint32_t hw[4], lw[4];
            cvt8(pb, hw, lw);
            int idx = brow0 * KTPB + bcol8;
            *(uint4*)(sBhi + idx) = make_uint4(hw[0], hw[1], hw[2], hw[3]);
            *(uint4*)(sBlo + idx) = make_uint4(lw[0], lw[1], lw[2], lw[3]);
        }
        if (i + 1 < nch) { issueA((i + 1) & 1, (ch0 + i + 1) * 32); CP_WAIT1(); }
        else             { CP_WAIT0(); }
        __syncthreads();

        if (i + 1 < nch) {   // prefetch next B (overlaps MMA)
            const float* q = vb + (size_t)((ch0 + i + 1) * 32 + brow0) * NPROJ + bcol8;
            *(float4*)&pb[0] = *(const float4*)q;
            *(float4*)&pb[4] = *(const float4*)(q + 4);
        }

        const __nv_bfloat16* baseA = sA + (i & 1) * KVA_STG;
#pragma unroll
        for (int ks = 0; ks < 2; ks++) {
            const int kc = ks * 16;
            uint32_t ahi[2][4], alo[2][4];
#pragma unroll
            for (int mi = 0; mi < 2; mi++) {
                const int off = (kc + r8 + (g8 >> 1) * 8) * KTP + wm + mi * 16 + (g8 & 1) * 8;
                ldmx4t(ahi[mi], baseA + off);
                ldmx4t(alo[mi], baseA + 32 * KTP + off);
            }
            uint32_t bhi[2][4], blo[2][4];
#pragma unroll
            for (int np = 0; np < 2; np++) {
                const int off = (kc + r8 + (g8 & 1) * 8) * KTPB + wn + np * 16 + (g8 >> 1) * 8;
                ldmx4t(bhi[np], sBhi + off);
                ldmx4t(blo[np], sBlo + off);
            }
#pragma unroll
            for (int mi = 0; mi < 2; mi++)
#pragma unroll
                for (int nj = 0; nj < 4; nj++) {
                    const int np = nj >> 1, o = (nj & 1) * 2;
                    mma16816(acc[mi][nj], ahi[mi], bhi[np][o], bhi[np][o+1]);
                    mma16816(acc[mi][nj], ahi[mi], blo[np][o], blo[np][o+1]);
                    mma16816(acc[mi][nj], alo[mi], bhi[np][o], bhi[np][o+1]);
                }
            if (blockIdx.x == 0 && wn == 0) {   // fused ksum from A fragments
#pragma unroll
                for (int mi = 0; mi < 2; mi++) {
                    ksm[mi][0] += bf_sum2(ahi[mi][0]) + bf_sum2(ahi[mi][2])
                                + bf_sum2(alo[mi][0]) + bf_sum2(alo[mi][2]);
                    ksm[mi][1] += bf_sum2(ahi[mi][1]) + bf_sum2(ahi[mi][3])
                                + bf_sum2(alo[mi][1]) + bf_sum2(alo[mi][3]);
                }
            }
        }
        __syncthreads();
    }

    const int rr0 = m0 + wm + (lane >> 2);
    const int cc0 = d0 + wn + (lane & 3) * 2;
#pragma unroll
    for (int mi = 0; mi < 2; mi++)
#pragma unroll
        for (int nj = 0; nj < 4; nj++) {
            int r = rr0 + mi * 16, c = cc0 + nj * 8;
            float* p0 = &g_kv[((size_t)b * TWOM + r) * DM + c];
            float* p1 = &g_kv[((size_t)b * TWOM + r + 8) * DM + c];
            atomicAdd(p0,     acc[mi][nj][0]);
            atomicAdd(p0 + 1, acc[mi][nj][1]);
            atomicAdd(p1,     acc[mi][nj][2]);
            atomicAdd(p1 + 1, acc[mi][nj][3]);
        }

    if (blockIdx.x == 0 && wn == 0) {
#pragma unroll
        for (int mi = 0; mi < 2; mi++) {
            float s0 = ksm[mi][0], s1 = ksm[mi][1];
            s0 += __shfl_xor_sync(0xFFFFFFFFu, s0, 1);
            s0 += __shfl_xor_sync(0xFFFFFFFFu, s0, 2);
            s1 += __shfl_xor_sync(0xFFFFFFFFu, s1, 1);
            s1 += __shfl_xor_sync(0xFFFFFFFFu, s1, 2);
            if ((lane & 3) == 0) {
                int m = m0 + wm + mi * 16 + (lane >> 2);
                atomicAdd(&g_ksum[b * TWOM + m],     s0);
                atomicAdd(&g_ksum[b * TWOM + m + 8], s1);
            }
        }
    }
}

// ============================================================================
// Kernel 5 (mma): num + fused denom + epilogue. Warp grid 4(m)x2(n), 32x32.
// ============================================================================
__global__ void __launch_bounds__(256, 2) k_num_mma(const float* __restrict__ b_add)
{
    __shared__ __nv_bfloat16 sAhi[128 * TPAD], sAlo[128 * TPAD];
    __shared__ __nv_bfloat16 sBhi[32 * KTPB],  sBlo[32 * KTPB];
    __shared__ float red2[128][4];

    const int d0 = blockIdx.x * 64;
    const int lt = blockIdx.y * 128;
    const int b  = blockIdx.z;
    const float* qpb = g_qp + (size_t)(b * LSEQ + lt) * TWOM;
    const float* kvb = g_kv + (size_t)b * TWOM * DM + d0;
    const float* ksb = g_ksum + b * TWOM;

    const int tid = threadIdx.x, wid = tid >> 5, lane = tid & 31;
    const int g8 = lane >> 3, r8 = lane & 7;
    const int wm = (wid >> 1) * 32, wn = (wid & 1) * 32;   // 4x2 warp grid
    const int arow = wm + (lane & 15);
    const int akc  = (lane >> 4) * 8;

    float acc[2][4][4] = {};
    float dn[2] = {0.f, 0.f};

    const int srow0 = tid >> 2, scol8 = (tid & 3) * 8;
    const int brow0 = tid >> 3, bcol8 = (tid & 7) * 8;

    float pa[2][8], pb[8];
#pragma unroll
    for (int i = 0; i < 2; i++) {
        const float* p = qpb + (size_t)(srow0 + i * 64) * TWOM + scol8;
        *(float4*)&pa[i][0] = *(const float4*)p;
        *(float4*)&pa[i][4] = *(const float4*)(p + 4);
    }
    {
        const float* q = kvb + (size_t)brow0 * DM + bcol8;
        *(float4*)&pb[0] = *(const float4*)q;
        *(float4*)&pb[4] = *(const float4*)(q + 4);
    }

    for (int ch = 0; ch < TWOM / 32; ch++) {
        const int k0 = ch * 32;
#pragma unroll
        for (int i = 0; i < 2; i++) {
            int row = srow0 + i * 64;
            uint32_t hw[4], lw[4];
            cvt8(pa[i], hw, lw);
            const float* ks = ksb + k0 + scol8;
#pragma unroll
            for (int q = 0; q < 8; q++) dn[i] = fmaf(pa[i][q], ks[q], dn[i]);
            *(uint4*)(sAhi + row * TPAD + scol8) = make_uint4(hw[0], hw[1], hw[2], hw[3]);
            *(uint4*)(sAlo + row * TPAD + scol8) = make_uint4(lw[0], lw[1], lw[2], lw[3]);
        }
        {
            uint32_t hw[4], lw[4];
            cvt8(pb, hw, lw);
            int idx = brow0 * KTPB + bcol8;
            *(uint4*)(sBhi + idx) = make_uint4(hw[0], hw[1], hw[2], hw[3]);
            *(uint4*)(sBlo + idx) = make_uint4(lw[0], lw[1], lw[2], lw[3]);
        }
        __syncthreads();

        if (ch + 1 < TWOM / 32) {
            const int k1 = (ch + 1) * 32;
#pragma unroll
            for (int i = 0; i < 2; i++) {
                const float* p = qpb + (size_t)(srow0 + i * 64) * TWOM + k1 + scol8;
                *(float4*)&pa[i][0] = *(const float4*)p;
                *(float4*)&pa[i][4] = *(const float4*)(p + 4);
            }
            const float* q = kvb + (size_t)(k1 + brow0) * DM + bcol8;
            *(float4*)&pb[0] = *(const float4*)q;
            *(float4*)&pb[4] = *(const float4*)(q + 4);
        }

#pragma unroll
        for (int ks2 = 0; ks2 < 2; ks2++) {
            const int kc = ks2 * 16;
            uint32_t ahi[2][4], alo[2][4];
#pragma unroll
            for (int mi = 0; mi < 2; mi++) {
                const int off = (arow + mi * 16) * TPAD + kc + akc;
                ldmx4(ahi[mi], sAhi + off);
                ldmx4(alo[mi], sAlo + off);
            }
            uint32_t bhi[2][4], blo[2][4];
#pragma unroll
            for (int np = 0; np < 2; np++) {
                const int off = (kc + r8 + (g8 & 1) * 8) * KTPB + wn + np * 16 + (g8 >> 1) * 8;
                ldmx4t(bhi[np], sBhi + off);
                ldmx4t(blo[np], sBlo + off);
            }
#pragma unroll
            for (int mi = 0; mi < 2; mi++)
#pragma unroll
                for (int nj = 0; nj < 4; nj++) {
                    const int np = nj >> 1, o = (nj & 1) * 2;
                    mma16816(acc[mi][nj], ahi[mi], bhi[np][o], bhi[np][o+1]);
                    mma16816(acc[mi][nj], ahi[mi], blo[np][o], blo[np][o+1]);
                    mma16816(acc[mi][nj], alo[mi], bhi[np][o], bhi[np][o+1]);
                }
        }
        __syncthreads();
    }

    red2[srow0][tid & 3]      = dn[0];
    red2[srow0 + 64][tid & 3] = dn[1];
    __syncthreads();

    const int rr0 = wm + (lane >> 2);
    const int cc0 = d0 + wn + (lane & 3) * 2;
#pragma unroll
    for (int mi = 0; mi < 2; mi++) {
#pragma unroll
        for (int h = 0; h < 2; h++) {
            int rloc = rr0 + mi * 16 + h * 8;
            float den = red2[rloc][0] + red2[rloc][1] + red2[rloc][2] + red2[rloc][3];
            float inv = 1.0f / den;
            int rg = b * LSEQ + lt + rloc;
            const float* addp = g_qkva + (size_t)rg * NPROJ + 3 * DM;
            float* orow = g_out + (size_t)rg * DM;
#pragma unroll
            for (int nj = 0; nj < 4; nj++) {
                int c = cc0 + nj * 8;
                float v0 = acc[mi][nj][h*2]   * inv + addp[c]     + b_add[c];
                float v1 = acc[mi][nj][h*2+1] * inv + addp[c + 1] + b_add[c + 1];
                *(float2*)&orow[c] = make_float2(v0, v1);
            }
        }
    }
}

// ============================================================================
// Kernel 6: final GEMM (split-K atomics; out pre-seeded with b_final by k_cvt)
// ============================================================================
__global__ void __launch_bounds__(256) k_final(const float* __restrict__ Wf,
                                               float* __restrict__ out)
{
    __shared__ float Ws[64][130];
    __shared__ float Os[8][132];

    const int tid = threadIdx.x;
    const int c  = tid & 63;
    const int bb = tid >> 6;
    float acc0 = 0.f, acc1 = 0.f;
    const int f0 = blockIdx.x * 1024;

    for (int t = 0; t < 1024; t += 128) {
        const int fbase = f0 + t;
#pragma unroll
        for (int i = 0; i < 8; i++) {
            int v = tid + i * 256;
            int cc = v >> 5, f4 = (v & 31) * 4;
            float4 w = *(const float4*)(Wf + (size_t)cc * FTOT + fbase + f4);
            Ws[cc][f4] = w.x; Ws[cc][f4+1] = w.y; Ws[cc][f4+2] = w.z; Ws[cc][f4+3] = w.w;
        }
        {
            int v = tid;
            int bo = v >> 5, f4 = (v & 31) * 4;
            float4 o = *(const float4*)(g_out + (size_t)bo * FTOT + fbase + f4);
            Os[bo][f4] = o.x; Os[bo][f4+1] = o.y; Os[bo][f4+2] = o.z; Os[bo][f4+3] = o.w;
        }
        __syncthreads();
#pragma unroll 8
        for (int fi = 0; fi < 128; fi++) {
            float w = Ws[c][fi];
            acc0 = fmaf(Os[bb][fi],     w, acc0);
            acc1 = fmaf(Os[bb + 4][fi], w, acc1);
        }
        __syncthreads();
    }
    atomicAdd(&out[bb * NCLASS + c],       acc0);
    atomicAdd(&out[(bb + 4) * NCLASS + c], acc1);
}

// ============================================================================
extern "C" void kernel_launch(void* const* d_in, const int* in_sizes, int n_in,
                              void* d_out, int out_size)
{
    const float* X  = (const float*)d_in[0];
    const float* Wq = (const float*)d_in[7];
    const float* Wk = (const float*)d_in[8];
    const float* Wv = (const float*)d_in[9];
    const float* Wa = (const float*)d_in[10];
    const float* bA = (const float*)d_in[11];
    const float* Wf = (const float*)d_in[12];
    const float* bF = (const float*)d_in[13];
    const float* rf = (const float*)d_in[14];
    float* out = (float*)d_out;

    static bool attr_done = false;
    if (!attr_done) {
        cudaFuncSetAttribute(k_proj_mma, cudaFuncAttributeMaxDynamicSharedMemorySize, SMEM_DYN2);
        cudaFuncSetAttribute(k_phi_mma,  cudaFuncAttributeMaxDynamicSharedMemorySize, SMEM_DYN2);
        attr_done = true;
    }

    k_cvt     <<<CVT_BLOCKS,      256>>>(X, Wq, Wk, Wv, Wa, rf, out, bF);
    k_proj_mma<<<dim3(8, 128),    256, SMEM_DYN2>>>();
    k_phi_mma <<<dim3(2, 128, 2), 256, SMEM_DYN2>>>();
    k_kv_mma  <<<dim3(4, 4, 8 * LSPLIT), 256>>>();
    k_num_mma <<<dim3(4, 16, 8),  256>>>(bA);
    k_final   <<<512, 256>>>(Wf, out);
}